// round 1
// baseline (speedup 1.0000x reference)
#include <cuda_runtime.h>
#include <cuda_bf16.h>

#define B_  512
#define D_  1024
#define H1_ 512
#define H2_ 128

// ---- scratch (device globals: allocation-free rule) ----
__device__ float g_c1 [B_ * H1_];
__device__ float g_s1p[B_ * H1_];
__device__ float g_s2p[B_ * H2_];
__device__ float g_c3 [B_ * H1_];

__device__ __forceinline__ float sigm(float v) { return 1.0f / (1.0f + expf(-v)); }

// ---- packed f32x2 helpers (sm_100+) ----
__device__ __forceinline__ unsigned long long dup_f32(float x) {
    unsigned long long r;
    unsigned int u = __float_as_uint(x);
    asm("mov.b64 %0, {%1, %1};" : "=l"(r) : "r"(u));
    return r;
}
__device__ __forceinline__ void fma2(unsigned long long& d,
                                     unsigned long long a, unsigned long long b) {
    asm("fma.rn.f32x2 %0, %1, %2, %0;" : "+l"(d) : "l"(a), "l"(b));
}
__device__ __forceinline__ unsigned long long mul2(unsigned long long a,
                                                   unsigned long long b) {
    unsigned long long r;
    asm("mul.rn.f32x2 %0, %1, %2;" : "=l"(r) : "l"(a), "l"(b));
    return r;
}

// ============================================================================
// Small generic SGEMM, 64x64x16 tiles, 256 threads, 4x4 microtile.
// TB=true : C[m,n] = act(sum_k A[m,k]*B[n,k] + bias[n])   (B is [N,K])
// TB=false: C[m,n] = act(sum_k A[m,k]*B[k,n] + bias[n])   (B is [K,N])
// ACT: 0 = identity, 1 = sigmoid, 2 = sigmoid + S = c*(1-c)
// All dims divide tile sizes exactly (checked at launch config).
// ============================================================================
template <int ACT, bool TB>
__global__ __launch_bounds__(256)
void sgemm64(const float* __restrict__ A, const float* __restrict__ Bm,
             const float* __restrict__ bias, float* __restrict__ C,
             float* __restrict__ S, int M, int N, int K) {
    constexpr int BM = 64, BN = 64, BK = 16;
    __shared__ __align__(16) float As[BK][BM + 4];
    __shared__ __align__(16) float Bs[BK][BN + 4];

    const int tid = threadIdx.x;
    const int m0 = blockIdx.y * BM;
    const int n0 = blockIdx.x * BN;

    const int ak = tid & 15;       // k within tile for A (and B when TB)
    const int am = tid >> 4;       // row-group base
    const int rowBase = (tid >> 4) * 4;
    const int colBase = (tid & 15) * 4;

    float acc[4][4] = {};
    float ra[4], rb[4];

    const int NT = K / BK;

    // ---- load tile t into registers ----
    auto loadA = [&](int t) {
        const int kt = t * BK;
#pragma unroll
        for (int j = 0; j < 4; j++)
            ra[j] = A[(size_t)(m0 + am + 16 * j) * K + kt + ak];
    };
    auto loadB = [&](int t) {
        const int kt = t * BK;
        if (TB) {
#pragma unroll
            for (int j = 0; j < 4; j++)
                rb[j] = Bm[(size_t)(n0 + am + 16 * j) * K + kt + ak];
        } else {
#pragma unroll
            for (int j = 0; j < 4; j++)
                rb[j] = Bm[(size_t)(kt + (tid >> 6) + 4 * j) * N + n0 + (tid & 63)];
        }
    };
    auto storeA = [&]() {
#pragma unroll
        for (int j = 0; j < 4; j++) As[ak][am + 16 * j] = ra[j];
    };
    auto storeB = [&]() {
        if (TB) {
#pragma unroll
            for (int j = 0; j < 4; j++) Bs[ak][am + 16 * j] = rb[j];
        } else {
#pragma unroll
            for (int j = 0; j < 4; j++) Bs[(tid >> 6) + 4 * j][tid & 63] = rb[j];
        }
    };

    loadA(0); loadB(0);
    storeA(); storeB();
    __syncthreads();

    for (int t = 0; t < NT; t++) {
        if (t + 1 < NT) { loadA(t + 1); loadB(t + 1); }
#pragma unroll
        for (int kk = 0; kk < BK; kk++) {
            float a[4], b[4];
            *(float4*)a = *(const float4*)&As[kk][rowBase];
            *(float4*)b = *(const float4*)&Bs[kk][colBase];
#pragma unroll
            for (int i = 0; i < 4; i++)
#pragma unroll
                for (int j = 0; j < 4; j++)
                    acc[i][j] += a[i] * b[j];
        }
        __syncthreads();
        if (t + 1 < NT) { storeA(); storeB(); __syncthreads(); }
    }

    // ---- epilogue ----
#pragma unroll
    for (int i = 0; i < 4; i++) {
        const int row = m0 + rowBase + i;
#pragma unroll
        for (int j = 0; j < 4; j++) {
            const int col = n0 + colBase + j;
            float v = acc[i][j] + bias[col];
            if (ACT == 0) {
                C[(size_t)row * N + col] = v;
            } else if (ACT == 1) {
                C[(size_t)row * N + col] = sigm(v);
            } else {
                float c = sigm(v);
                C[(size_t)row * N + col] = c;
                S[(size_t)row * N + col] = c * (1.0f - c);
            }
        }
    }
}

// ============================================================================
// Jac batched GEMM: for batch b,
//   Jac[b,h,d] = s2p[b,h] * sum_k (W2[h,k] * s1p[b,k]) * W1[k,d]
// One CTA = 128(M=H2 full) x 128(N) x K=512 slab. grid = (D/128, B).
// Packed f32x2 FMA microkernel: 8x8 per-thread tile as 8 rows x 4 f32x2 pairs.
// ============================================================================
__global__ __launch_bounds__(256, 2)
void jac_kernel(const float* __restrict__ W2, const float* __restrict__ W1,
                const float* __restrict__ s1p, const float* __restrict__ s2p,
                float* __restrict__ jac) {
    constexpr int BM = 128, BN = 128, BK = 8;
    __shared__ __align__(16) float As[BK][BM + 4];
    __shared__ __align__(16) float Bs[BK][BN + 4];

    const int b  = blockIdx.y;
    const int n0 = blockIdx.x * BN;
    const int tid = threadIdx.x;

    const float* __restrict__ s1 = s1p + (size_t)b * H1_;

    const int ak = tid & 7;        // A: k fast
    const int am = tid >> 3;       // A: row base (0..31), rows am+32j
    const int bk = tid >> 7;       // B: k base (0..1), ks bk+2j
    const int bn = tid & 127;      // B: col

    const int rowBase = (tid >> 4) * 8;
    const int colBase = (tid & 15) * 8;

    unsigned long long acc[8][4] = {};
    float ra[4], rb[4];

    constexpr int NT = H1_ / BK;   // 64

    // tile 0
    {
#pragma unroll
        for (int j = 0; j < 4; j++)
            ra[j] = W2[(size_t)(am + 32 * j) * H1_ + ak] * s1[ak];
#pragma unroll
        for (int j = 0; j < 4; j++)
            rb[j] = W1[(size_t)(bk + 2 * j) * D_ + n0 + bn];
#pragma unroll
        for (int j = 0; j < 4; j++) As[ak][am + 32 * j] = ra[j];
#pragma unroll
        for (int j = 0; j < 4; j++) Bs[bk + 2 * j][bn] = rb[j];
    }
    __syncthreads();

    for (int t = 0; t < NT; t++) {
        if (t + 1 < NT) {
            const int kt = (t + 1) * BK;
#pragma unroll
            for (int j = 0; j < 4; j++)
                ra[j] = W2[(size_t)(am + 32 * j) * H1_ + kt + ak] * s1[kt + ak];
#pragma unroll
            for (int j = 0; j < 4; j++)
                rb[j] = W1[(size_t)(kt + bk + 2 * j) * D_ + n0 + bn];
        }

#pragma unroll
        for (int kk = 0; kk < BK; kk++) {
            float4 a0 = *(const float4*)&As[kk][rowBase];
            float4 a1 = *(const float4*)&As[kk][rowBase + 4];
            ulonglong2 bv0 = *(const ulonglong2*)&Bs[kk][colBase];
            ulonglong2 bv1 = *(const ulonglong2*)&Bs[kk][colBase + 4];
            unsigned long long bp[4] = {bv0.x, bv0.y, bv1.x, bv1.y};
            float av[8] = {a0.x, a0.y, a0.z, a0.w, a1.x, a1.y, a1.z, a1.w};
#pragma unroll
            for (int i = 0; i < 8; i++) {
                unsigned long long ad = dup_f32(av[i]);
#pragma unroll
                for (int j = 0; j < 4; j++) fma2(acc[i][j], ad, bp[j]);
            }
        }
        __syncthreads();
        if (t + 1 < NT) {
#pragma unroll
            for (int j = 0; j < 4; j++) As[ak][am + 32 * j] = ra[j];
#pragma unroll
            for (int j = 0; j < 4; j++) Bs[bk + 2 * j][bn] = rb[j];
            __syncthreads();
        }
    }

    // epilogue: scale by s2p[b,row], vector stores
    float* base = jac + (size_t)b * H2_ * D_ + n0 + colBase;
#pragma unroll
    for (int i = 0; i < 8; i++) {
        const int row = rowBase + i;
        unsigned long long sd = dup_f32(s2p[(size_t)b * H2_ + row]);
        unsigned long long r0 = mul2(acc[i][0], sd);
        unsigned long long r1 = mul2(acc[i][1], sd);
        unsigned long long r2 = mul2(acc[i][2], sd);
        unsigned long long r3 = mul2(acc[i][3], sd);
        ulonglong2* p = (ulonglong2*)(base + (size_t)row * D_);
        p[0] = make_ulonglong2(r0, r1);
        p[1] = make_ulonglong2(r2, r3);
    }
}

// ============================================================================
extern "C" void kernel_launch(void* const* d_in, const int* in_sizes, int n_in,
                              void* d_out, int out_size) {
    const float* x   = (const float*)d_in[0];
    const float* W1  = (const float*)d_in[1];
    const float* b1  = (const float*)d_in[2];
    const float* W2  = (const float*)d_in[3];
    const float* b2  = (const float*)d_in[4];
    const float* b3  = (const float*)d_in[5];
    const float* b_r = (const float*)d_in[6];

    float* out     = (float*)d_out;
    float* recover = out;                              // [B, D]
    float* c2      = out + (size_t)B_ * D_;            // [B, H2]
    float* jac     = c2 + (size_t)B_ * H2_;            // [B, H2, D]

    float *c1, *s1p, *s2p, *c3;
    cudaGetSymbolAddress((void**)&c1,  g_c1);
    cudaGetSymbolAddress((void**)&s1p, g_s1p);
    cudaGetSymbolAddress((void**)&s2p, g_s2p);
    cudaGetSymbolAddress((void**)&c3,  g_c3);

    dim3 blk(256);

    // c1 = sigmoid(x @ W1^T + b1); s1p = c1*(1-c1)     [512x512, K=1024]
    sgemm64<2, true><<<dim3(H1_ / 64, B_ / 64), blk>>>(x, W1, b1, c1, s1p,
                                                       B_, H1_, D_);
    // c2 = sigmoid(c1 @ W2^T + b2); s2p = c2*(1-c2)    [512x128, K=512]
    sgemm64<2, true><<<dim3(H2_ / 64, B_ / 64), blk>>>(c1, W2, b2, c2, s2p,
                                                       B_, H2_, H1_);
    // c3 = sigmoid(c2 @ W2 + b3)                        [512x512, K=128]
    sgemm64<1, false><<<dim3(H1_ / 64, B_ / 64), blk>>>(c2, W2, b3, c3, nullptr,
                                                        B_, H1_, H2_);
    // recover = c3 @ W1 + b_r                           [512x1024, K=512]
    sgemm64<0, false><<<dim3(D_ / 64, B_ / 64), blk>>>(c3, W1, b_r, recover,
                                                       nullptr, B_, D_, H1_);
    // Jac                                               [512 x (128x1024), K=512]
    jac_kernel<<<dim3(D_ / 128, B_), blk>>>(W2, W1, s1p, s2p, jac);
}

// round 2
// speedup vs baseline: 1.0009x; 1.0009x over previous
#include <cuda_runtime.h>
#include <cuda_bf16.h>

#define B_  512
#define D_  1024
#define H1_ 512
#define H2_ 128

// ---- scratch (device globals: allocation-free rule) ----
__device__ float g_c1 [B_ * H1_];
__device__ float g_s1p[B_ * H1_];
__device__ float g_s2p[B_ * H2_];
__device__ float g_c3 [B_ * H1_];

__device__ __forceinline__ float sigm(float v) { return 1.0f / (1.0f + expf(-v)); }

// ---- packed f32x2 helpers (sm_100+) ----
__device__ __forceinline__ unsigned long long dup_f32(float x) {
    unsigned long long r;
    unsigned int u = __float_as_uint(x);
    asm("mov.b64 %0, {%1, %1};" : "=l"(r) : "r"(u));
    return r;
}
__device__ __forceinline__ void fma2(unsigned long long& d,
                                     unsigned long long a, unsigned long long b) {
    asm("fma.rn.f32x2 %0, %1, %2, %0;" : "+l"(d) : "l"(a), "l"(b));
}
__device__ __forceinline__ unsigned long long mul2(unsigned long long a,
                                                   unsigned long long b) {
    unsigned long long r;
    asm("mul.rn.f32x2 %0, %1, %2;" : "=l"(r) : "l"(a), "l"(b));
    return r;
}

// ============================================================================
// Small generic SGEMM, 64x64x16 tiles, 256 threads, 4x4 microtile.
// TB=true : C[m,n] = act(sum_k A[m,k]*B[n,k] + bias[n])   (B is [N,K])
// TB=false: C[m,n] = act(sum_k A[m,k]*B[k,n] + bias[n])   (B is [K,N])
// ACT: 0 = identity, 1 = sigmoid, 2 = sigmoid + S = c*(1-c)
// All dims divide tile sizes exactly (checked at launch config).
// ============================================================================
template <int ACT, bool TB>
__global__ __launch_bounds__(256)
void sgemm64(const float* __restrict__ A, const float* __restrict__ Bm,
             const float* __restrict__ bias, float* __restrict__ C,
             float* __restrict__ S, int M, int N, int K) {
    constexpr int BM = 64, BN = 64, BK = 16;
    __shared__ __align__(16) float As[BK][BM + 4];
    __shared__ __align__(16) float Bs[BK][BN + 4];

    const int tid = threadIdx.x;
    const int m0 = blockIdx.y * BM;
    const int n0 = blockIdx.x * BN;

    const int ak = tid & 15;       // k within tile for A (and B when TB)
    const int am = tid >> 4;       // row-group base
    const int rowBase = (tid >> 4) * 4;
    const int colBase = (tid & 15) * 4;

    float acc[4][4] = {};
    float ra[4], rb[4];

    const int NT = K / BK;

    // ---- load tile t into registers ----
    auto loadA = [&](int t) {
        const int kt = t * BK;
#pragma unroll
        for (int j = 0; j < 4; j++)
            ra[j] = A[(size_t)(m0 + am + 16 * j) * K + kt + ak];
    };
    auto loadB = [&](int t) {
        const int kt = t * BK;
        if (TB) {
#pragma unroll
            for (int j = 0; j < 4; j++)
                rb[j] = Bm[(size_t)(n0 + am + 16 * j) * K + kt + ak];
        } else {
#pragma unroll
            for (int j = 0; j < 4; j++)
                rb[j] = Bm[(size_t)(kt + (tid >> 6) + 4 * j) * N + n0 + (tid & 63)];
        }
    };
    auto storeA = [&]() {
#pragma unroll
        for (int j = 0; j < 4; j++) As[ak][am + 16 * j] = ra[j];
    };
    auto storeB = [&]() {
        if (TB) {
#pragma unroll
            for (int j = 0; j < 4; j++) Bs[ak][am + 16 * j] = rb[j];
        } else {
#pragma unroll
            for (int j = 0; j < 4; j++) Bs[(tid >> 6) + 4 * j][tid & 63] = rb[j];
        }
    };

    loadA(0); loadB(0);
    storeA(); storeB();
    __syncthreads();

    for (int t = 0; t < NT; t++) {
        if (t + 1 < NT) { loadA(t + 1); loadB(t + 1); }
#pragma unroll
        for (int kk = 0; kk < BK; kk++) {
            float a[4], b[4];
            *(float4*)a = *(const float4*)&As[kk][rowBase];
            *(float4*)b = *(const float4*)&Bs[kk][colBase];
#pragma unroll
            for (int i = 0; i < 4; i++)
#pragma unroll
                for (int j = 0; j < 4; j++)
                    acc[i][j] += a[i] * b[j];
        }
        __syncthreads();
        if (t + 1 < NT) { storeA(); storeB(); __syncthreads(); }
    }

    // ---- epilogue ----
#pragma unroll
    for (int i = 0; i < 4; i++) {
        const int row = m0 + rowBase + i;
#pragma unroll
        for (int j = 0; j < 4; j++) {
            const int col = n0 + colBase + j;
            float v = acc[i][j] + bias[col];
            if (ACT == 0) {
                C[(size_t)row * N + col] = v;
            } else if (ACT == 1) {
                C[(size_t)row * N + col] = sigm(v);
            } else {
                float c = sigm(v);
                C[(size_t)row * N + col] = c;
                S[(size_t)row * N + col] = c * (1.0f - c);
            }
        }
    }
}

// ============================================================================
// Jac batched GEMM: for batch b,
//   Jac[b,h,d] = s2p[b,h] * sum_k (W2[h,k] * s1p[b,k]) * W1[k,d]
// One CTA = 128(M=H2 full) x 128(N) x K=512 slab. grid = (D/128, B).
// Packed f32x2 FMA microkernel: 8x8 per-thread tile as 8 rows x 4 f32x2 pairs.
// ============================================================================
__global__ __launch_bounds__(256, 2)
void jac_kernel(const float* __restrict__ W2, const float* __restrict__ W1,
                const float* __restrict__ s1p, const float* __restrict__ s2p,
                float* __restrict__ jac) {
    constexpr int BM = 128, BN = 128, BK = 8;
    __shared__ __align__(16) float As[BK][BM + 4];
    __shared__ __align__(16) float Bs[BK][BN + 4];

    const int b  = blockIdx.y;
    const int n0 = blockIdx.x * BN;
    const int tid = threadIdx.x;

    const float* __restrict__ s1 = s1p + (size_t)b * H1_;

    const int ak = tid & 7;        // A: k fast
    const int am = tid >> 3;       // A: row base (0..31), rows am+32j
    const int bk = tid >> 7;       // B: k base (0..1), ks bk+2j
    const int bn = tid & 127;      // B: col

    const int rowBase = (tid >> 4) * 8;
    const int colBase = (tid & 15) * 8;

    unsigned long long acc[8][4] = {};
    float ra[4], rb[4];

    constexpr int NT = H1_ / BK;   // 64

    // tile 0
    {
#pragma unroll
        for (int j = 0; j < 4; j++)
            ra[j] = W2[(size_t)(am + 32 * j) * H1_ + ak] * s1[ak];
#pragma unroll
        for (int j = 0; j < 4; j++)
            rb[j] = W1[(size_t)(bk + 2 * j) * D_ + n0 + bn];
#pragma unroll
        for (int j = 0; j < 4; j++) As[ak][am + 32 * j] = ra[j];
#pragma unroll
        for (int j = 0; j < 4; j++) Bs[bk + 2 * j][bn] = rb[j];
    }
    __syncthreads();

    for (int t = 0; t < NT; t++) {
        if (t + 1 < NT) {
            const int kt = (t + 1) * BK;
#pragma unroll
            for (int j = 0; j < 4; j++)
                ra[j] = W2[(size_t)(am + 32 * j) * H1_ + kt + ak] * s1[kt + ak];
#pragma unroll
            for (int j = 0; j < 4; j++)
                rb[j] = W1[(size_t)(kt + bk + 2 * j) * D_ + n0 + bn];
        }

#pragma unroll
        for (int kk = 0; kk < BK; kk++) {
            float4 a0 = *(const float4*)&As[kk][rowBase];
            float4 a1 = *(const float4*)&As[kk][rowBase + 4];
            ulonglong2 bv0 = *(const ulonglong2*)&Bs[kk][colBase];
            ulonglong2 bv1 = *(const ulonglong2*)&Bs[kk][colBase + 4];
            unsigned long long bp[4] = {bv0.x, bv0.y, bv1.x, bv1.y};
            float av[8] = {a0.x, a0.y, a0.z, a0.w, a1.x, a1.y, a1.z, a1.w};
#pragma unroll
            for (int i = 0; i < 8; i++) {
                unsigned long long ad = dup_f32(av[i]);
#pragma unroll
                for (int j = 0; j < 4; j++) fma2(acc[i][j], ad, bp[j]);
            }
        }
        __syncthreads();
        if (t + 1 < NT) {
#pragma unroll
            for (int j = 0; j < 4; j++) As[ak][am + 32 * j] = ra[j];
#pragma unroll
            for (int j = 0; j < 4; j++) Bs[bk + 2 * j][bn] = rb[j];
            __syncthreads();
        }
    }

    // epilogue: scale by s2p[b,row], vector stores
    float* base = jac + (size_t)b * H2_ * D_ + n0 + colBase;
#pragma unroll
    for (int i = 0; i < 8; i++) {
        const int row = rowBase + i;
        unsigned long long sd = dup_f32(s2p[(size_t)b * H2_ + row]);
        unsigned long long r0 = mul2(acc[i][0], sd);
        unsigned long long r1 = mul2(acc[i][1], sd);
        unsigned long long r2 = mul2(acc[i][2], sd);
        unsigned long long r3 = mul2(acc[i][3], sd);
        ulonglong2* p = (ulonglong2*)(base + (size_t)row * D_);
        p[0] = make_ulonglong2(r0, r1);
        p[1] = make_ulonglong2(r2, r3);
    }
}

// ============================================================================
extern "C" void kernel_launch(void* const* d_in, const int* in_sizes, int n_in,
                              void* d_out, int out_size) {
    const float* x   = (const float*)d_in[0];
    const float* W1  = (const float*)d_in[1];
    const float* b1  = (const float*)d_in[2];
    const float* W2  = (const float*)d_in[3];
    const float* b2  = (const float*)d_in[4];
    const float* b3  = (const float*)d_in[5];
    const float* b_r = (const float*)d_in[6];

    float* out     = (float*)d_out;
    float* recover = out;                              // [B, D]
    float* c2      = out + (size_t)B_ * D_;            // [B, H2]
    float* jac     = c2 + (size_t)B_ * H2_;            // [B, H2, D]

    float *c1, *s1p, *s2p, *c3;
    cudaGetSymbolAddress((void**)&c1,  g_c1);
    cudaGetSymbolAddress((void**)&s1p, g_s1p);
    cudaGetSymbolAddress((void**)&s2p, g_s2p);
    cudaGetSymbolAddress((void**)&c3,  g_c3);

    dim3 blk(256);

    // c1 = sigmoid(x @ W1^T + b1); s1p = c1*(1-c1)     [512x512, K=1024]
    sgemm64<2, true><<<dim3(H1_ / 64, B_ / 64), blk>>>(x, W1, b1, c1, s1p,
                                                       B_, H1_, D_);
    // c2 = sigmoid(c1 @ W2^T + b2); s2p = c2*(1-c2)    [512x128, K=512]
    sgemm64<2, true><<<dim3(H2_ / 64, B_ / 64), blk>>>(c1, W2, b2, c2, s2p,
                                                       B_, H2_, H1_);
    // c3 = sigmoid(c2 @ W2 + b3)                        [512x512, K=128]
    sgemm64<1, false><<<dim3(H1_ / 64, B_ / 64), blk>>>(c2, W2, b3, c3, nullptr,
                                                        B_, H1_, H2_);
    // recover = c3 @ W1 + b_r                           [512x1024, K=512]
    sgemm64<0, false><<<dim3(D_ / 64, B_ / 64), blk>>>(c3, W1, b_r, recover,
                                                       nullptr, B_, D_, H1_);
    // Jac                                               [512 x (128x1024), K=512]
    jac_kernel<<<dim3(D_ / 128, B_), blk>>>(W2, W1, s1p, s2p, jac);
}

// round 4
// speedup vs baseline: 1.9441x; 1.9423x over previous
#include <cuda_runtime.h>
#include <cuda_bf16.h>
#include <cstdint>

#define B_  512
#define D_  1024
#define H1_ 512
#define H2_ 128

// ---- scratch (device globals: allocation-free rule) ----
__device__ float g_c1 [B_ * H1_];
__device__ float g_s1p[B_ * H1_];
__device__ float g_s2p[B_ * H2_];
__device__ float g_c3 [B_ * H1_];
__device__ __nv_bfloat16 g_w1t_hi[D_ * H1_];           // W1^T split, [D][H1]
__device__ __nv_bfloat16 g_w1t_lo[D_ * H1_];
__device__ __nv_bfloat16 g_a_hi[(size_t)B_ * H2_ * H1_];  // (W2 . s1p[b]) split
__device__ __nv_bfloat16 g_a_lo[(size_t)B_ * H2_ * H1_];

__device__ __forceinline__ float sigm(float v) { return 1.0f / (1.0f + expf(-v)); }

__device__ __forceinline__ uint32_t smem_u32(const void* p) {
    uint32_t a;
    asm("{ .reg .u64 t; cvta.to.shared.u64 t, %1; cvt.u32.u64 %0, t; }" : "=r"(a) : "l"(p));
    return a;
}
__device__ __forceinline__ uint32_t pack2(float a, float b) {
    __nv_bfloat162 t = __floats2bfloat162_rn(a, b);
    return *reinterpret_cast<uint32_t*>(&t);
}
__device__ __forceinline__ void cp16(uint32_t dst, const void* src) {
    asm volatile("cp.async.cg.shared.global [%0], [%1], 16;" :: "r"(dst), "l"(src));
}
__device__ __forceinline__ void ldm_x4(uint32_t* r, uint32_t addr) {
    asm volatile("ldmatrix.sync.aligned.m8n8.x4.shared.b16 {%0,%1,%2,%3}, [%4];"
                 : "=r"(r[0]), "=r"(r[1]), "=r"(r[2]), "=r"(r[3]) : "r"(addr));
}
__device__ __forceinline__ void mma_bf16(float* c, const uint32_t* a,
                                         uint32_t b0, uint32_t b1) {
    asm volatile("mma.sync.aligned.m16n8k16.row.col.f32.bf16.bf16.f32 "
                 "{%0,%1,%2,%3}, {%4,%5,%6,%7}, {%8,%9}, {%0,%1,%2,%3};"
                 : "+f"(c[0]), "+f"(c[1]), "+f"(c[2]), "+f"(c[3])
                 : "r"(a[0]), "r"(a[1]), "r"(a[2]), "r"(a[3]), "r"(b0), "r"(b1));
}

// ============================================================================
// W1 split+transpose: W1 [H1, D] f32  ->  W1T_hi/lo [D, H1] bf16
// ============================================================================
__global__ __launch_bounds__(256)
void w1_split_kernel(const float* __restrict__ W1,
                     __nv_bfloat16* __restrict__ hi, __nv_bfloat16* __restrict__ lo) {
    __shared__ float t[32][33];
    const int tx = threadIdx.x, ty = threadIdx.y;
    const int k0 = blockIdx.x * 32, d0 = blockIdx.y * 32;
#pragma unroll
    for (int j = 0; j < 4; j++)
        t[ty + 8 * j][tx] = W1[(size_t)(k0 + ty + 8 * j) * D_ + d0 + tx];
    __syncthreads();
#pragma unroll
    for (int j = 0; j < 4; j++) {
        const int dr = ty + 8 * j;
        float v = t[tx][dr];
        __nv_bfloat16 h = __float2bfloat16_rn(v);
        float r = v - __bfloat162float(h);
        hi[(size_t)(d0 + dr) * H1_ + k0 + tx] = h;
        lo[(size_t)(d0 + dr) * H1_ + k0 + tx] = __float2bfloat16_rn(r);
    }
}

// ============================================================================
// A split: A[b,h,k] = W2[h,k] * s1p[b,k] -> bf16 hi/lo globals.
// 8 elements per thread, 16B vector stores.
// ============================================================================
__global__ __launch_bounds__(256)
void a_split_kernel(const float* __restrict__ W2, const float* __restrict__ s1p,
                    __nv_bfloat16* __restrict__ hi, __nv_bfloat16* __restrict__ lo) {
    const size_t idx = ((size_t)blockIdx.x * 256 + threadIdx.x) * 8;
    const int k = (int)(idx & (H1_ - 1));
    const int h = (int)((idx >> 9) & (H2_ - 1));
    const int b = (int)(idx >> 16);
    const float* wr = W2 + (size_t)h * H1_ + k;
    const float* sr = s1p + (size_t)b * H1_ + k;
    float4 w0 = *(const float4*)wr;
    float4 w1 = *(const float4*)(wr + 4);
    float4 q0 = *(const float4*)sr;
    float4 q1 = *(const float4*)(sr + 4);
    float v[8] = {w0.x * q0.x, w0.y * q0.y, w0.z * q0.z, w0.w * q0.w,
                  w1.x * q1.x, w1.y * q1.y, w1.z * q1.z, w1.w * q1.w};
    uint32_t hp[4], lp[4];
#pragma unroll
    for (int j = 0; j < 4; j++) {
        float a = v[2 * j], c = v[2 * j + 1];
        __nv_bfloat16 ha = __float2bfloat16_rn(a);
        __nv_bfloat16 hc = __float2bfloat16_rn(c);
        hp[j] = pack2(a, c);
        lp[j] = pack2(a - __bfloat162float(ha), c - __bfloat162float(hc));
    }
    *(uint4*)(hi + idx) = make_uint4(hp[0], hp[1], hp[2], hp[3]);
    *(uint4*)(lo + idx) = make_uint4(lp[0], lp[1], lp[2], lp[3]);
}

// ============================================================================
// Jac GEMM via mma.sync bf16 (split precision, 3 passes into fp32 accum).
// CTA = (batch b, 128-wide n tile): C[128,128] = A'[128,512] @ W1T^T[512,128].
// BK=32, double-buffered cp.async. 8 warps, warp tile 64x32.
// SMEM stage: Ah|Al|Bh|Bl, each [128][32] bf16 padded to 40 (80B rows).
// ============================================================================
static constexpr int TILE_B = 10240;           // one [128][40] bf16 tile
static constexpr int STAGE_B = 4 * TILE_B;     // 40960
static constexpr int JAC_SMEM = 2 * STAGE_B;   // 81920

__global__ __launch_bounds__(256, 1)
void jac_mma_kernel(const __nv_bfloat16* __restrict__ a_hi,
                    const __nv_bfloat16* __restrict__ a_lo,
                    const __nv_bfloat16* __restrict__ w1t_hi,
                    const __nv_bfloat16* __restrict__ w1t_lo,
                    const float* __restrict__ s2p,
                    float* __restrict__ jac) {
    extern __shared__ char smem[];
    const uint32_t sb = smem_u32(smem);
    const int tid = threadIdx.x;
    const int wid = tid >> 5;
    const int lane = tid & 31;
    const int wm = wid >> 2;           // 0..1  (64 rows each)
    const int wn = wid & 3;            // 0..3  (32 cols each)
    const int b  = blockIdx.y;
    const int n0 = blockIdx.x * 128;

    const __nv_bfloat16* Ah = a_hi + (size_t)b * (H2_ * H1_);
    const __nv_bfloat16* Al = a_lo + (size_t)b * (H2_ * H1_);
    const __nv_bfloat16* Bh = w1t_hi + (size_t)n0 * H1_;
    const __nv_bfloat16* Bl = w1t_lo + (size_t)n0 * H1_;

    float acc[4][4][4] = {};

    // ---- async stage loader: 4 tiles x 512 16B-chunks, 8 chunks/thread ----
    auto load_stage = [&](int it, int st) {
        const int k0 = it * 32;
        const uint32_t base = sb + st * STAGE_B;
#pragma unroll
        for (int T = 0; T < 4; T++) {
            const __nv_bfloat16* src0 =
                (T == 0 ? Ah : T == 1 ? Al : T == 2 ? Bh : Bl) + k0;
#pragma unroll
            for (int hf = 0; hf < 2; hf++) {
                const int c = hf * 256 + tid;      // 0..511
                const int row = c >> 2, seg = c & 3;
                cp16(base + T * TILE_B + row * 80 + seg * 16,
                     src0 + (size_t)row * H1_ + seg * 8);
            }
        }
        asm volatile("cp.async.commit_group;");
    };

    // ldmatrix lane addressing (within a stage)
    const int mi = lane >> 3;
    const int a_r  = (lane & 7) + 8 * (mi & 1);
    const int a_cb = (mi >> 1) * 16;
    const int b_r  = (mi >> 1) * 8 + (lane & 7);
    const int b_cb = (mi & 1) * 16;

    load_stage(0, 0);

    for (int it = 0; it < 16; it++) {
        const int st = it & 1;
        if (it + 1 < 16) load_stage(it + 1, st ^ 1);
        if (it + 1 < 16) asm volatile("cp.async.wait_group 1;");
        else             asm volatile("cp.async.wait_group 0;");
        __syncthreads();

        const uint32_t stage = sb + st * STAGE_B;
#pragma unroll
        for (int ks = 0; ks < 2; ks++) {
            const int kb2 = ks * 32;               // byte offset of k-step
            uint32_t ah[4][4], al[4][4], bh[2][4], bl[2][4];
#pragma unroll
            for (int mt = 0; mt < 4; mt++) {
                const uint32_t ao = (uint32_t)((wm * 64 + mt * 16 + a_r) * 80 + kb2 + a_cb);
                ldm_x4(ah[mt], stage + 0 * TILE_B + ao);
                ldm_x4(al[mt], stage + 1 * TILE_B + ao);
            }
#pragma unroll
            for (int np = 0; np < 2; np++) {
                const uint32_t bo = (uint32_t)((wn * 32 + np * 16 + b_r) * 80 + kb2 + b_cb);
                ldm_x4(bh[np], stage + 2 * TILE_B + bo);
                ldm_x4(bl[np], stage + 3 * TILE_B + bo);
            }
#pragma unroll
            for (int mt = 0; mt < 4; mt++)
#pragma unroll
                for (int nt = 0; nt < 4; nt++) {
                    const int hp = nt >> 1, hq = (nt & 1) * 2;
                    mma_bf16(acc[mt][nt], ah[mt], bh[hp][hq], bh[hp][hq + 1]);
                    mma_bf16(acc[mt][nt], ah[mt], bl[hp][hq], bl[hp][hq + 1]);
                    mma_bf16(acc[mt][nt], al[mt], bh[hp][hq], bh[hp][hq + 1]);
                }
        }
        __syncthreads();
    }

    // ---- epilogue: scale rows by s2p[b,row], store float2 ----
    const int g = lane >> 2;
    const int cq = 2 * (lane & 3);
#pragma unroll
    for (int mt = 0; mt < 4; mt++) {
        const int r0 = wm * 64 + mt * 16 + g;
        const float s0 = s2p[(size_t)b * H2_ + r0];
        const float s1 = s2p[(size_t)b * H2_ + r0 + 8];
        float* row0 = jac + ((size_t)b * H2_ + r0) * D_ + n0;
        float* row1 = row0 + 8 * D_;
#pragma unroll
        for (int nt = 0; nt < 4; nt++) {
            const int col = wn * 32 + nt * 8 + cq;
            float2 v0 = make_float2(acc[mt][nt][0] * s0, acc[mt][nt][1] * s0);
            float2 v1 = make_float2(acc[mt][nt][2] * s1, acc[mt][nt][3] * s1);
            *(float2*)(row0 + col) = v0;
            *(float2*)(row1 + col) = v1;
        }
    }
}

// ============================================================================
// Small generic SGEMM, 64x64x16 tiles, 256 threads, 4x4 microtile (unchanged).
// ============================================================================
template <int ACT, bool TB>
__global__ __launch_bounds__(256)
void sgemm64(const float* __restrict__ A, const float* __restrict__ Bm,
             const float* __restrict__ bias, float* __restrict__ C,
             float* __restrict__ S, int M, int N, int K) {
    constexpr int BM = 64, BN = 64, BK = 16;
    __shared__ __align__(16) float As[BK][BM + 4];
    __shared__ __align__(16) float Bs[BK][BN + 4];

    const int tid = threadIdx.x;
    const int m0 = blockIdx.y * BM;
    const int n0 = blockIdx.x * BN;

    const int ak = tid & 15;
    const int am = tid >> 4;
    const int rowBase = (tid >> 4) * 4;
    const int colBase = (tid & 15) * 4;

    float acc[4][4] = {};
    float ra[4], rb[4];
    const int NT = K / BK;

    auto loadA = [&](int t) {
        const int kt = t * BK;
#pragma unroll
        for (int j = 0; j < 4; j++)
            ra[j] = A[(size_t)(m0 + am + 16 * j) * K + kt + ak];
    };
    auto loadB = [&](int t) {
        const int kt = t * BK;
        if (TB) {
#pragma unroll
            for (int j = 0; j < 4; j++)
                rb[j] = Bm[(size_t)(n0 + am + 16 * j) * K + kt + ak];
        } else {
#pragma unroll
            for (int j = 0; j < 4; j++)
                rb[j] = Bm[(size_t)(kt + (tid >> 6) + 4 * j) * N + n0 + (tid & 63)];
        }
    };
    auto storeA = [&]() {
#pragma unroll
        for (int j = 0; j < 4; j++) As[ak][am + 16 * j] = ra[j];
    };
    auto storeB = [&]() {
        if (TB) {
#pragma unroll
            for (int j = 0; j < 4; j++) Bs[ak][am + 16 * j] = rb[j];
        } else {
#pragma unroll
            for (int j = 0; j < 4; j++) Bs[(tid >> 6) + 4 * j][tid & 63] = rb[j];
        }
    };

    loadA(0); loadB(0);
    storeA(); storeB();
    __syncthreads();

    for (int t = 0; t < NT; t++) {
        if (t + 1 < NT) { loadA(t + 1); loadB(t + 1); }
#pragma unroll
        for (int kk = 0; kk < BK; kk++) {
            float a[4], bq[4];
            *(float4*)a  = *(const float4*)&As[kk][rowBase];
            *(float4*)bq = *(const float4*)&Bs[kk][colBase];
#pragma unroll
            for (int i = 0; i < 4; i++)
#pragma unroll
                for (int j = 0; j < 4; j++)
                    acc[i][j] += a[i] * bq[j];
        }
        __syncthreads();
        if (t + 1 < NT) { storeA(); storeB(); __syncthreads(); }
    }

#pragma unroll
    for (int i = 0; i < 4; i++) {
        const int row = m0 + rowBase + i;
#pragma unroll
        for (int j = 0; j < 4; j++) {
            const int col = n0 + colBase + j;
            float v = acc[i][j] + bias[col];
            if (ACT == 0) {
                C[(size_t)row * N + col] = v;
            } else if (ACT == 1) {
                C[(size_t)row * N + col] = sigm(v);
            } else {
                float c = sigm(v);
                C[(size_t)row * N + col] = c;
                S[(size_t)row * N + col] = c * (1.0f - c);
            }
        }
    }
}

// ============================================================================
extern "C" void kernel_launch(void* const* d_in, const int* in_sizes, int n_in,
                              void* d_out, int out_size) {
    const float* x   = (const float*)d_in[0];
    const float* W1  = (const float*)d_in[1];
    const float* b1  = (const float*)d_in[2];
    const float* W2  = (const float*)d_in[3];
    const float* b2  = (const float*)d_in[4];
    const float* b3  = (const float*)d_in[5];
    const float* b_r = (const float*)d_in[6];

    float* out     = (float*)d_out;
    float* recover = out;                              // [B, D]
    float* c2      = out + (size_t)B_ * D_;            // [B, H2]
    float* jac     = c2 + (size_t)B_ * H2_;            // [B, H2, D]

    float *c1, *s1p, *s2p, *c3;
    __nv_bfloat16 *w1t_hi, *w1t_lo, *a_hi, *a_lo;
    cudaGetSymbolAddress((void**)&c1,  g_c1);
    cudaGetSymbolAddress((void**)&s1p, g_s1p);
    cudaGetSymbolAddress((void**)&s2p, g_s2p);
    cudaGetSymbolAddress((void**)&c3,  g_c3);
    cudaGetSymbolAddress((void**)&w1t_hi, g_w1t_hi);
    cudaGetSymbolAddress((void**)&w1t_lo, g_w1t_lo);
    cudaGetSymbolAddress((void**)&a_hi, g_a_hi);
    cudaGetSymbolAddress((void**)&a_lo, g_a_lo);

    cudaFuncSetAttribute(jac_mma_kernel,
                         cudaFuncAttributeMaxDynamicSharedMemorySize, JAC_SMEM);

    dim3 blk(256);

    // W1 -> W1T hi/lo bf16 split (independent of activations)
    w1_split_kernel<<<dim3(H1_ / 32, D_ / 32), dim3(32, 8)>>>(W1, w1t_hi, w1t_lo);

    // c1 = sigmoid(x @ W1^T + b1); s1p = c1*(1-c1)     [512x512, K=1024]
    sgemm64<2, true><<<dim3(H1_ / 64, B_ / 64), blk>>>(x, W1, b1, c1, s1p,
                                                       B_, H1_, D_);
    // c2 = sigmoid(c1 @ W2^T + b2); s2p = c2*(1-c2)    [512x128, K=512]
    sgemm64<2, true><<<dim3(H2_ / 64, B_ / 64), blk>>>(c1, W2, b2, c2, s2p,
                                                       B_, H2_, H1_);
    // A[b] = W2 . s1p[b] -> bf16 hi/lo
    a_split_kernel<<<(int)(((size_t)B_ * H2_ * H1_) / 8 / 256), blk>>>(W2, s1p,
                                                                       a_hi, a_lo);
    // Jac via mma.sync                                 [512 x (128x1024), K=512]
    jac_mma_kernel<<<dim3(D_ / 128, B_), blk, JAC_SMEM>>>(a_hi, a_lo,
                                                          w1t_hi, w1t_lo, s2p, jac);
    // c3 = sigmoid(c2 @ W2 + b3)                        [512x512, K=128]
    sgemm64<1, false><<<dim3(H1_ / 64, B_ / 64), blk>>>(c2, W2, b3, c3, nullptr,
                                                        B_, H1_, H2_);
    // recover = c3 @ W1 + b_r                           [512x1024, K=512]
    sgemm64<0, false><<<dim3(D_ / 64, B_ / 64), blk>>>(c3, W1, b_r, recover,
                                                       nullptr, B_, D_, H1_);
}

// round 5
// speedup vs baseline: 2.1188x; 1.0898x over previous
#include <cuda_runtime.h>
#include <cuda_bf16.h>
#include <cstdint>

#define B_  512
#define D_  1024
#define H1_ 512
#define H2_ 128

// ---- scratch (device globals: allocation-free rule) ----
__device__ float g_c1 [B_ * H1_];
__device__ float g_s1p[B_ * H1_];
__device__ float g_s2p[B_ * H2_];
__device__ float g_c3 [B_ * H1_];
__device__ __nv_bfloat16 g_w1t_hi[D_ * H1_];           // W1^T split, [D][H1]
__device__ __nv_bfloat16 g_w1t_lo[D_ * H1_];
__device__ __nv_bfloat16 g_a_hi[(size_t)B_ * H2_ * H1_];  // (W2 . s1p[b]) split
__device__ __nv_bfloat16 g_a_lo[(size_t)B_ * H2_ * H1_];

__device__ __forceinline__ float sigm(float v) { return 1.0f / (1.0f + expf(-v)); }

__device__ __forceinline__ uint32_t smem_u32(const void* p) {
    uint32_t a;
    asm("{ .reg .u64 t; cvta.to.shared.u64 t, %1; cvt.u32.u64 %0, t; }" : "=r"(a) : "l"(p));
    return a;
}
__device__ __forceinline__ uint32_t pack2(float a, float b) {
    __nv_bfloat162 t = __floats2bfloat162_rn(a, b);
    return *reinterpret_cast<uint32_t*>(&t);
}
__device__ __forceinline__ void cp16(uint32_t dst, const void* src) {
    asm volatile("cp.async.cg.shared.global [%0], [%1], 16;" :: "r"(dst), "l"(src));
}
__device__ __forceinline__ void ldm_x4(uint32_t* r, uint32_t addr) {
    asm volatile("ldmatrix.sync.aligned.m8n8.x4.shared.b16 {%0,%1,%2,%3}, [%4];"
                 : "=r"(r[0]), "=r"(r[1]), "=r"(r[2]), "=r"(r[3]) : "r"(addr));
}
__device__ __forceinline__ void mma_bf16(float* c, const uint32_t* a,
                                         uint32_t b0, uint32_t b1) {
    asm volatile("mma.sync.aligned.m16n8k16.row.col.f32.bf16.bf16.f32 "
                 "{%0,%1,%2,%3}, {%4,%5,%6,%7}, {%8,%9}, {%0,%1,%2,%3};"
                 : "+f"(c[0]), "+f"(c[1]), "+f"(c[2]), "+f"(c[3])
                 : "r"(a[0]), "r"(a[1]), "r"(a[2]), "r"(a[3]), "r"(b0), "r"(b1));
}

// ============================================================================
// W1 split+transpose: W1 [H1, D] f32  ->  W1T_hi/lo [D, H1] bf16
// ============================================================================
__global__ __launch_bounds__(256)
void w1_split_kernel(const float* __restrict__ W1,
                     __nv_bfloat16* __restrict__ hi, __nv_bfloat16* __restrict__ lo) {
    __shared__ float t[32][33];
    const int tx = threadIdx.x, ty = threadIdx.y;
    const int k0 = blockIdx.x * 32, d0 = blockIdx.y * 32;
#pragma unroll
    for (int j = 0; j < 4; j++)
        t[ty + 8 * j][tx] = W1[(size_t)(k0 + ty + 8 * j) * D_ + d0 + tx];
    __syncthreads();
#pragma unroll
    for (int j = 0; j < 4; j++) {
        const int dr = ty + 8 * j;
        float v = t[tx][dr];
        __nv_bfloat16 h = __float2bfloat16_rn(v);
        float r = v - __bfloat162float(h);
        hi[(size_t)(d0 + dr) * H1_ + k0 + tx] = h;
        lo[(size_t)(d0 + dr) * H1_ + k0 + tx] = __float2bfloat16_rn(r);
    }
}

// ============================================================================
// A split: A[b,h,k] = W2[h,k] * s1p[b,k] -> bf16 hi/lo globals.
// ============================================================================
__global__ __launch_bounds__(256)
void a_split_kernel(const float* __restrict__ W2, const float* __restrict__ s1p,
                    __nv_bfloat16* __restrict__ hi, __nv_bfloat16* __restrict__ lo) {
    const size_t idx = ((size_t)blockIdx.x * 256 + threadIdx.x) * 8;
    const int k = (int)(idx & (H1_ - 1));
    const int h = (int)((idx >> 9) & (H2_ - 1));
    const int b = (int)(idx >> 16);
    const float* wr = W2 + (size_t)h * H1_ + k;
    const float* sr = s1p + (size_t)b * H1_ + k;
    float4 w0 = *(const float4*)wr;
    float4 w1 = *(const float4*)(wr + 4);
    float4 q0 = *(const float4*)sr;
    float4 q1 = *(const float4*)(sr + 4);
    float v[8] = {w0.x * q0.x, w0.y * q0.y, w0.z * q0.z, w0.w * q0.w,
                  w1.x * q1.x, w1.y * q1.y, w1.z * q1.z, w1.w * q1.w};
    uint32_t hp[4], lp[4];
#pragma unroll
    for (int j = 0; j < 4; j++) {
        float a = v[2 * j], c = v[2 * j + 1];
        __nv_bfloat16 ha = __float2bfloat16_rn(a);
        __nv_bfloat16 hc = __float2bfloat16_rn(c);
        hp[j] = pack2(a, c);
        lp[j] = pack2(a - __bfloat162float(ha), c - __bfloat162float(hc));
    }
    *(uint4*)(hi + idx) = make_uint4(hp[0], hp[1], hp[2], hp[3]);
    *(uint4*)(lo + idx) = make_uint4(lp[0], lp[1], lp[2], lp[3]);
}

// ============================================================================
// Jac GEMM via mma.sync bf16, split precision (Ah*Bh + Ah*Bl + Al*Bh).
// CTA = (batch b, 256-wide n tile): C[128,256] = A'[128,512] @ W1T^T[512,256].
// BK=32, 3-stage cp.async pipeline, ONE __syncthreads per k-iter.
// 8 warps, warp tile 64x64.
// Stage: Ah[128][40] | Al[128][40] | Bh[256][40] | Bl[256][40]  (bf16, 80B rows)
// ============================================================================
static constexpr int A_TILE  = 10240;          // 128*40*2
static constexpr int BT_TILE = 20480;          // 256*40*2
static constexpr int STAGE_B = 2 * A_TILE + 2 * BT_TILE;   // 61440
static constexpr int JAC_SMEM = 3 * STAGE_B;               // 184320

__global__ __launch_bounds__(256, 1)
void jac_mma_kernel(const __nv_bfloat16* __restrict__ a_hi,
                    const __nv_bfloat16* __restrict__ a_lo,
                    const __nv_bfloat16* __restrict__ w1t_hi,
                    const __nv_bfloat16* __restrict__ w1t_lo,
                    const float* __restrict__ s2p,
                    float* __restrict__ jac) {
    extern __shared__ char smem[];
    const uint32_t sb = smem_u32(smem);
    const int tid = threadIdx.x;
    const int wid = tid >> 5;
    const int lane = tid & 31;
    const int wm = wid >> 2;           // 0..1  (64 rows each)
    const int wn = wid & 3;            // 0..3  (64 cols each)
    const int b  = blockIdx.y;
    const int n0 = blockIdx.x * 256;

    const __nv_bfloat16* Ah = a_hi + (size_t)b * (H2_ * H1_);
    const __nv_bfloat16* Al = a_lo + (size_t)b * (H2_ * H1_);
    const __nv_bfloat16* Bh = w1t_hi + (size_t)n0 * H1_;
    const __nv_bfloat16* Bl = w1t_lo + (size_t)n0 * H1_;

    float acc[4][8][4] = {};

    // ---- async stage loader: 3072 16B data chunks, 12 per thread ----
    // chunk map: [0,512) Ah | [512,1024) Al | [1024,2048) Bh | [2048,3072) Bl
    auto load_stage = [&](int it, int slot) {
        const int k0 = it * 32;
        const uint32_t base = sb + slot * STAGE_B;
#pragma unroll
        for (int q = 0; q < 12; q++) {
            const int c = tid + q * 256;
            const __nv_bfloat16* src;
            uint32_t dst;
            if (c < 1024) {                       // A tiles: 128 rows
                const int ci = c & 511;
                const int row = ci >> 2, seg = ci & 3;
                src = (c < 512 ? Ah : Al) + (size_t)row * H1_ + k0 + seg * 8;
                dst = base + (c < 512 ? 0 : A_TILE) + row * 80 + seg * 16;
            } else {                              // B tiles: 256 rows
                const int ci = (c - 1024) & 1023;
                const int row = ci >> 2, seg = ci & 3;
                src = (c < 2048 ? Bh : Bl) + (size_t)row * H1_ + k0 + seg * 8;
                dst = base + 2 * A_TILE + (c < 2048 ? 0 : BT_TILE)
                      + row * 80 + seg * 16;
            }
            cp16(dst, src);
        }
        asm volatile("cp.async.commit_group;" ::: "memory");
    };

    // ldmatrix lane addressing
    const int mi = lane >> 3;
    const int a_r  = (lane & 7) + 8 * (mi & 1);
    const int a_cb = (mi >> 1) * 16;
    const int b_r  = (mi >> 1) * 8 + (lane & 7);
    const int b_cb = (mi & 1) * 16;

    load_stage(0, 0);
    load_stage(1, 1);

    for (int it = 0; it < 16; it++) {
        if (it < 14) asm volatile("cp.async.wait_group 1;" ::: "memory");
        else         asm volatile("cp.async.wait_group 0;" ::: "memory");
        __syncthreads();

        if (it + 2 < 16) load_stage(it + 2, (it + 2) % 3);

        const uint32_t stage = sb + (it % 3) * STAGE_B;
#pragma unroll
        for (int ks = 0; ks < 2; ks++) {
            const int kb2 = ks * 32;               // byte offset of k-step
            uint32_t ah[4][4], al[4][4], bh[4][4], bl[4][4];
#pragma unroll
            for (int mt = 0; mt < 4; mt++) {
                const uint32_t ao = (uint32_t)((wm * 64 + mt * 16 + a_r) * 80 + kb2 + a_cb);
                ldm_x4(ah[mt], stage + ao);
                ldm_x4(al[mt], stage + A_TILE + ao);
            }
#pragma unroll
            for (int np = 0; np < 4; np++) {
                const uint32_t bo = (uint32_t)((wn * 64 + np * 16 + b_r) * 80 + kb2 + b_cb);
                ldm_x4(bh[np], stage + 2 * A_TILE + bo);
                ldm_x4(bl[np], stage + 2 * A_TILE + BT_TILE + bo);
            }
#pragma unroll
            for (int mt = 0; mt < 4; mt++)
#pragma unroll
                for (int nt = 0; nt < 8; nt++) {
                    const int np = nt >> 1, hq = (nt & 1) * 2;
                    mma_bf16(acc[mt][nt], ah[mt], bh[np][hq], bh[np][hq + 1]);
                    mma_bf16(acc[mt][nt], ah[mt], bl[np][hq], bl[np][hq + 1]);
                    mma_bf16(acc[mt][nt], al[mt], bh[np][hq], bh[np][hq + 1]);
                }
        }
    }

    // ---- epilogue: scale rows by s2p[b,row], store float2 ----
    const int g = lane >> 2;
    const int cq = 2 * (lane & 3);
#pragma unroll
    for (int mt = 0; mt < 4; mt++) {
        const int r0 = wm * 64 + mt * 16 + g;
        const float s0 = s2p[(size_t)b * H2_ + r0];
        const float s1 = s2p[(size_t)b * H2_ + r0 + 8];
        float* row0 = jac + ((size_t)b * H2_ + r0) * D_ + n0;
        float* row1 = row0 + 8 * D_;
#pragma unroll
        for (int nt = 0; nt < 8; nt++) {
            const int col = wn * 64 + nt * 8 + cq;
            float2 v0 = make_float2(acc[mt][nt][0] * s0, acc[mt][nt][1] * s0);
            float2 v1 = make_float2(acc[mt][nt][2] * s1, acc[mt][nt][3] * s1);
            *(float2*)(row0 + col) = v0;
            *(float2*)(row1 + col) = v1;
        }
    }
}

// ============================================================================
// Small generic SGEMM, 64x64x16 tiles, 256 threads, 4x4 microtile (unchanged).
// ============================================================================
template <int ACT, bool TB>
__global__ __launch_bounds__(256)
void sgemm64(const float* __restrict__ A, const float* __restrict__ Bm,
             const float* __restrict__ bias, float* __restrict__ C,
             float* __restrict__ S, int M, int N, int K) {
    constexpr int BM = 64, BN = 64, BK = 16;
    __shared__ __align__(16) float As[BK][BM + 4];
    __shared__ __align__(16) float Bs[BK][BN + 4];

    const int tid = threadIdx.x;
    const int m0 = blockIdx.y * BM;
    const int n0 = blockIdx.x * BN;

    const int ak = tid & 15;
    const int am = tid >> 4;
    const int rowBase = (tid >> 4) * 4;
    const int colBase = (tid & 15) * 4;

    float acc[4][4] = {};
    float ra[4], rb[4];
    const int NT = K / BK;

    auto loadA = [&](int t) {
        const int kt = t * BK;
#pragma unroll
        for (int j = 0; j < 4; j++)
            ra[j] = A[(size_t)(m0 + am + 16 * j) * K + kt + ak];
    };
    auto loadB = [&](int t) {
        const int kt = t * BK;
        if (TB) {
#pragma unroll
            for (int j = 0; j < 4; j++)
                rb[j] = Bm[(size_t)(n0 + am + 16 * j) * K + kt + ak];
        } else {
#pragma unroll
            for (int j = 0; j < 4; j++)
                rb[j] = Bm[(size_t)(kt + (tid >> 6) + 4 * j) * N + n0 + (tid & 63)];
        }
    };
    auto storeA = [&]() {
#pragma unroll
        for (int j = 0; j < 4; j++) As[ak][am + 16 * j] = ra[j];
    };
    auto storeB = [&]() {
        if (TB) {
#pragma unroll
            for (int j = 0; j < 4; j++) Bs[ak][am + 16 * j] = rb[j];
        } else {
#pragma unroll
            for (int j = 0; j < 4; j++) Bs[(tid >> 6) + 4 * j][tid & 63] = rb[j];
        }
    };

    loadA(0); loadB(0);
    storeA(); storeB();
    __syncthreads();

    for (int t = 0; t < NT; t++) {
        if (t + 1 < NT) { loadA(t + 1); loadB(t + 1); }
#pragma unroll
        for (int kk = 0; kk < BK; kk++) {
            float a[4], bq[4];
            *(float4*)a  = *(const float4*)&As[kk][rowBase];
            *(float4*)bq = *(const float4*)&Bs[kk][colBase];
#pragma unroll
            for (int i = 0; i < 4; i++)
#pragma unroll
                for (int j = 0; j < 4; j++)
                    acc[i][j] += a[i] * bq[j];
        }
        __syncthreads();
        if (t + 1 < NT) { storeA(); storeB(); __syncthreads(); }
    }

#pragma unroll
    for (int i = 0; i < 4; i++) {
        const int row = m0 + rowBase + i;
#pragma unroll
        for (int j = 0; j < 4; j++) {
            const int col = n0 + colBase + j;
            float v = acc[i][j] + bias[col];
            if (ACT == 0) {
                C[(size_t)row * N + col] = v;
            } else if (ACT == 1) {
                C[(size_t)row * N + col] = sigm(v);
            } else {
                float c = sigm(v);
                C[(size_t)row * N + col] = c;
                S[(size_t)row * N + col] = c * (1.0f - c);
            }
        }
    }
}

// ============================================================================
extern "C" void kernel_launch(void* const* d_in, const int* in_sizes, int n_in,
                              void* d_out, int out_size) {
    const float* x   = (const float*)d_in[0];
    const float* W1  = (const float*)d_in[1];
    const float* b1  = (const float*)d_in[2];
    const float* W2  = (const float*)d_in[3];
    const float* b2  = (const float*)d_in[4];
    const float* b3  = (const float*)d_in[5];
    const float* b_r = (const float*)d_in[6];

    float* out     = (float*)d_out;
    float* recover = out;                              // [B, D]
    float* c2      = out + (size_t)B_ * D_;            // [B, H2]
    float* jac     = c2 + (size_t)B_ * H2_;            // [B, H2, D]

    float *c1, *s1p, *s2p, *c3;
    __nv_bfloat16 *w1t_hi, *w1t_lo, *a_hi, *a_lo;
    cudaGetSymbolAddress((void**)&c1,  g_c1);
    cudaGetSymbolAddress((void**)&s1p, g_s1p);
    cudaGetSymbolAddress((void**)&s2p, g_s2p);
    cudaGetSymbolAddress((void**)&c3,  g_c3);
    cudaGetSymbolAddress((void**)&w1t_hi, g_w1t_hi);
    cudaGetSymbolAddress((void**)&w1t_lo, g_w1t_lo);
    cudaGetSymbolAddress((void**)&a_hi, g_a_hi);
    cudaGetSymbolAddress((void**)&a_lo, g_a_lo);

    cudaFuncSetAttribute(jac_mma_kernel,
                         cudaFuncAttributeMaxDynamicSharedMemorySize, JAC_SMEM);

    dim3 blk(256);

    // W1 -> W1T hi/lo bf16 split (independent of activations)
    w1_split_kernel<<<dim3(H1_ / 32, D_ / 32), dim3(32, 8)>>>(W1, w1t_hi, w1t_lo);

    // c1 = sigmoid(x @ W1^T + b1); s1p = c1*(1-c1)     [512x512, K=1024]
    sgemm64<2, true><<<dim3(H1_ / 64, B_ / 64), blk>>>(x, W1, b1, c1, s1p,
                                                       B_, H1_, D_);
    // c2 = sigmoid(c1 @ W2^T + b2); s2p = c2*(1-c2)    [512x128, K=512]
    sgemm64<2, true><<<dim3(H2_ / 64, B_ / 64), blk>>>(c1, W2, b2, c2, s2p,
                                                       B_, H2_, H1_);
    // A[b] = W2 . s1p[b] -> bf16 hi/lo
    a_split_kernel<<<(int)(((size_t)B_ * H2_ * H1_) / 8 / 256), blk>>>(W2, s1p,
                                                                       a_hi, a_lo);
    // Jac via mma.sync                                 [512 x (128x1024), K=512]
    jac_mma_kernel<<<dim3(D_ / 256, B_), blk, JAC_SMEM>>>(a_hi, a_lo,
                                                          w1t_hi, w1t_lo, s2p, jac);
    // c3 = sigmoid(c2 @ W2 + b3)                        [512x512, K=128]
    sgemm64<1, false><<<dim3(H1_ / 64, B_ / 64), blk>>>(c2, W2, b3, c3, nullptr,
                                                        B_, H1_, H2_);
    // recover = c3 @ W1 + b_r                           [512x1024, K=512]
    sgemm64<0, false><<<dim3(D_ / 64, B_ / 64), blk>>>(c3, W1, b_r, recover,
                                                       nullptr, B_, D_, H1_);
}

// round 6
// speedup vs baseline: 2.6735x; 1.2618x over previous
#include <cuda_runtime.h>
#include <cuda_fp16.h>
#include <cstdint>

#define B_  512
#define D_  1024
#define H1_ 512
#define H2_ 128

// ---- scratch (device globals: allocation-free rule) ----
__device__ float g_c1 [B_ * H1_];
__device__ float g_s1p[B_ * H1_];
__device__ float g_s2p[B_ * H2_];
__device__ float g_c3 [B_ * H1_];
__device__ __half g_w1t_hi[D_ * H1_];                  // W1^T split, [D][H1]
__device__ __half g_w1t_lo[D_ * H1_];
__device__ __half g_a_hi[(size_t)B_ * H2_ * H1_];      // fp16(W2 . s1p[b])

__device__ __forceinline__ float sigm(float v) { return 1.0f / (1.0f + expf(-v)); }

__device__ __forceinline__ uint32_t smem_u32(const void* p) {
    uint32_t a;
    asm("{ .reg .u64 t; cvta.to.shared.u64 t, %1; cvt.u32.u64 %0, t; }" : "=r"(a) : "l"(p));
    return a;
}
__device__ __forceinline__ uint32_t packh2(float a, float b) {
    __half2 t = __floats2half2_rn(a, b);
    return *reinterpret_cast<uint32_t*>(&t);
}
__device__ __forceinline__ void cp16(uint32_t dst, const void* src) {
    asm volatile("cp.async.cg.shared.global [%0], [%1], 16;" :: "r"(dst), "l"(src));
}
__device__ __forceinline__ void ldm_x4(uint32_t* r, uint32_t addr) {
    asm volatile("ldmatrix.sync.aligned.m8n8.x4.shared.b16 {%0,%1,%2,%3}, [%4];"
                 : "=r"(r[0]), "=r"(r[1]), "=r"(r[2]), "=r"(r[3]) : "r"(addr));
}
__device__ __forceinline__ void mma_f16(float* c, const uint32_t* a,
                                        uint32_t b0, uint32_t b1) {
    asm volatile("mma.sync.aligned.m16n8k16.row.col.f32.f16.f16.f32 "
                 "{%0,%1,%2,%3}, {%4,%5,%6,%7}, {%8,%9}, {%0,%1,%2,%3};"
                 : "+f"(c[0]), "+f"(c[1]), "+f"(c[2]), "+f"(c[3])
                 : "r"(a[0]), "r"(a[1]), "r"(a[2]), "r"(a[3]), "r"(b0), "r"(b1));
}

// ============================================================================
// W1 split+transpose: W1 [H1, D] f32  ->  W1T_hi/lo [D, H1] fp16
// ============================================================================
__global__ __launch_bounds__(256)
void w1_split_kernel(const float* __restrict__ W1,
                     __half* __restrict__ hi, __half* __restrict__ lo) {
    __shared__ float t[32][33];
    const int tx = threadIdx.x, ty = threadIdx.y;
    const int k0 = blockIdx.x * 32, d0 = blockIdx.y * 32;
#pragma unroll
    for (int j = 0; j < 4; j++)
        t[ty + 8 * j][tx] = W1[(size_t)(k0 + ty + 8 * j) * D_ + d0 + tx];
    __syncthreads();
#pragma unroll
    for (int j = 0; j < 4; j++) {
        const int dr = ty + 8 * j;
        float v = t[tx][dr];
        __half h = __float2half_rn(v);
        float r = v - __half2float(h);
        hi[(size_t)(d0 + dr) * H1_ + k0 + tx] = h;
        lo[(size_t)(d0 + dr) * H1_ + k0 + tx] = __float2half_rn(r);
    }
}

// ============================================================================
// A split: A[b,h,k] = fp16(W2[h,k] * s1p[b,k])  (hi only; lo pass dropped)
// ============================================================================
__global__ __launch_bounds__(256)
void a_split_kernel(const float* __restrict__ W2, const float* __restrict__ s1p,
                    __half* __restrict__ hi) {
    const size_t idx = ((size_t)blockIdx.x * 256 + threadIdx.x) * 8;
    const int k = (int)(idx & (H1_ - 1));
    const int h = (int)((idx >> 9) & (H2_ - 1));
    const int b = (int)(idx >> 16);
    const float* wr = W2 + (size_t)h * H1_ + k;
    const float* sr = s1p + (size_t)b * H1_ + k;
    float4 w0 = *(const float4*)wr;
    float4 w1 = *(const float4*)(wr + 4);
    float4 q0 = *(const float4*)sr;
    float4 q1 = *(const float4*)(sr + 4);
    uint32_t hp[4];
    hp[0] = packh2(w0.x * q0.x, w0.y * q0.y);
    hp[1] = packh2(w0.z * q0.z, w0.w * q0.w);
    hp[2] = packh2(w1.x * q1.x, w1.y * q1.y);
    hp[3] = packh2(w1.z * q1.z, w1.w * q1.w);
    *(uint4*)(hi + idx) = make_uint4(hp[0], hp[1], hp[2], hp[3]);
}

// ============================================================================
// Jac GEMM via mma.sync fp16, 2-pass split precision: D = Ah*Bh + Ah*Bl.
// CTA = (batch b, 256-wide n tile): C[128,256] = A'[128,512] @ W1T^T[512,256].
// BK=32, 3-stage cp.async pipeline, ONE __syncthreads per k-iter.
// 8 warps, warp tile 64x64.
// Stage: Ah[128][40] | Bh[256][40] | Bl[256][40]   (fp16, 80B padded rows)
// ============================================================================
static constexpr int A_TILE  = 10240;          // 128*40*2
static constexpr int BT_TILE = 20480;          // 256*40*2
static constexpr int STAGE_B = A_TILE + 2 * BT_TILE;       // 51200
static constexpr int JAC_SMEM = 3 * STAGE_B;               // 153600

__global__ __launch_bounds__(256, 1)
void jac_mma_kernel(const __half* __restrict__ a_hi,
                    const __half* __restrict__ w1t_hi,
                    const __half* __restrict__ w1t_lo,
                    const float* __restrict__ s2p,
                    float* __restrict__ jac) {
    extern __shared__ char smem[];
    const uint32_t sb = smem_u32(smem);
    const int tid = threadIdx.x;
    const int wid = tid >> 5;
    const int lane = tid & 31;
    const int wm = wid >> 2;           // 0..1  (64 rows each)
    const int wn = wid & 3;            // 0..3  (64 cols each)
    const int b  = blockIdx.y;
    const int n0 = blockIdx.x * 256;

    const __half* Ah = a_hi + (size_t)b * (H2_ * H1_);
    const __half* Bh = w1t_hi + (size_t)n0 * H1_;
    const __half* Bl = w1t_lo + (size_t)n0 * H1_;

    float acc[4][8][4] = {};

    // ---- async stage loader: 2560 16B chunks, 10 per thread ----
    // map: [0,512) Ah | [512,1536) Bh | [1536,2560) Bl
    auto load_stage = [&](int it, int slot) {
        const int k0 = it * 32;
        const uint32_t base = sb + slot * STAGE_B;
#pragma unroll
        for (int q = 0; q < 10; q++) {
            const int c = tid + q * 256;
            const __half* src;
            uint32_t dst;
            if (c < 512) {                        // Ah: 128 rows x 4 segs
                const int row = c >> 2, seg = c & 3;
                src = Ah + (size_t)row * H1_ + k0 + seg * 8;
                dst = base + row * 80 + seg * 16;
            } else {                              // B tiles: 256 rows x 4 segs
                const int c2 = c - 512;
                const int split = c2 >> 10;       // 0=Bh, 1=Bl
                const int ci = c2 & 1023;
                const int row = ci >> 2, seg = ci & 3;
                src = (split ? Bl : Bh) + (size_t)row * H1_ + k0 + seg * 8;
                dst = base + A_TILE + split * BT_TILE + row * 80 + seg * 16;
            }
            cp16(dst, src);
        }
        asm volatile("cp.async.commit_group;" ::: "memory");
    };

    // ldmatrix lane addressing
    const int mi = lane >> 3;
    const int a_r  = (lane & 7) + 8 * (mi & 1);
    const int a_cb = (mi >> 1) * 16;
    const int b_r  = (mi >> 1) * 8 + (lane & 7);
    const int b_cb = (mi & 1) * 16;

    load_stage(0, 0);
    load_stage(1, 1);

    for (int it = 0; it < 16; it++) {
        if (it < 14) asm volatile("cp.async.wait_group 1;" ::: "memory");
        else         asm volatile("cp.async.wait_group 0;" ::: "memory");
        __syncthreads();

        if (it + 2 < 16) load_stage(it + 2, (it + 2) % 3);

        const uint32_t stage = sb + (it % 3) * STAGE_B;
#pragma unroll
        for (int ks = 0; ks < 2; ks++) {
            const int kb2 = ks * 32;               // byte offset of k-step
            uint32_t ah[4][4], bh[4][4], bl[4][4];
#pragma unroll
            for (int mt = 0; mt < 4; mt++) {
                const uint32_t ao = (uint32_t)((wm * 64 + mt * 16 + a_r) * 80 + kb2 + a_cb);
                ldm_x4(ah[mt], stage + ao);
            }
#pragma unroll
            for (int np = 0; np < 4; np++) {
                const uint32_t bo = (uint32_t)((wn * 64 + np * 16 + b_r) * 80 + kb2 + b_cb);
                ldm_x4(bh[np], stage + A_TILE + bo);
                ldm_x4(bl[np], stage + A_TILE + BT_TILE + bo);
            }
#pragma unroll
            for (int mt = 0; mt < 4; mt++)
#pragma unroll
                for (int nt = 0; nt < 8; nt++) {
                    const int np = nt >> 1, hq = (nt & 1) * 2;
                    mma_f16(acc[mt][nt], ah[mt], bh[np][hq], bh[np][hq + 1]);
                    mma_f16(acc[mt][nt], ah[mt], bl[np][hq], bl[np][hq + 1]);
                }
        }
    }

    // ---- epilogue: scale rows by s2p[b,row], store float2 ----
    const int g = lane >> 2;
    const int cq = 2 * (lane & 3);
#pragma unroll
    for (int mt = 0; mt < 4; mt++) {
        const int r0 = wm * 64 + mt * 16 + g;
        const float s0 = s2p[(size_t)b * H2_ + r0];
        const float s1 = s2p[(size_t)b * H2_ + r0 + 8];
        float* row0 = jac + ((size_t)b * H2_ + r0) * D_ + n0;
        float* row1 = row0 + 8 * D_;
#pragma unroll
        for (int nt = 0; nt < 8; nt++) {
            const int col = wn * 64 + nt * 8 + cq;
            float2 v0 = make_float2(acc[mt][nt][0] * s0, acc[mt][nt][1] * s0);
            float2 v1 = make_float2(acc[mt][nt][2] * s1, acc[mt][nt][3] * s1);
            *(float2*)(row0 + col) = v0;
            *(float2*)(row1 + col) = v1;
        }
    }
}

// ============================================================================
// Small generic SGEMM, 64x64x16 tiles, 256 threads, 4x4 microtile (unchanged).
// ============================================================================
template <int ACT, bool TB>
__global__ __launch_bounds__(256)
void sgemm64(const float* __restrict__ A, const float* __restrict__ Bm,
             const float* __restrict__ bias, float* __restrict__ C,
             float* __restrict__ S, int M, int N, int K) {
    constexpr int BM = 64, BN = 64, BK = 16;
    __shared__ __align__(16) float As[BK][BM + 4];
    __shared__ __align__(16) float Bs[BK][BN + 4];

    const int tid = threadIdx.x;
    const int m0 = blockIdx.y * BM;
    const int n0 = blockIdx.x * BN;

    const int ak = tid & 15;
    const int am = tid >> 4;
    const int rowBase = (tid >> 4) * 4;
    const int colBase = (tid & 15) * 4;

    float acc[4][4] = {};
    float ra[4], rb[4];
    const int NT = K / BK;

    auto loadA = [&](int t) {
        const int kt = t * BK;
#pragma unroll
        for (int j = 0; j < 4; j++)
            ra[j] = A[(size_t)(m0 + am + 16 * j) * K + kt + ak];
    };
    auto loadB = [&](int t) {
        const int kt = t * BK;
        if (TB) {
#pragma unroll
            for (int j = 0; j < 4; j++)
                rb[j] = Bm[(size_t)(n0 + am + 16 * j) * K + kt + ak];
        } else {
#pragma unroll
            for (int j = 0; j < 4; j++)
                rb[j] = Bm[(size_t)(kt + (tid >> 6) + 4 * j) * N + n0 + (tid & 63)];
        }
    };
    auto storeA = [&]() {
#pragma unroll
        for (int j = 0; j < 4; j++) As[ak][am + 16 * j] = ra[j];
    };
    auto storeB = [&]() {
        if (TB) {
#pragma unroll
            for (int j = 0; j < 4; j++) Bs[ak][am + 16 * j] = rb[j];
        } else {
#pragma unroll
            for (int j = 0; j < 4; j++) Bs[(tid >> 6) + 4 * j][tid & 63] = rb[j];
        }
    };

    loadA(0); loadB(0);
    storeA(); storeB();
    __syncthreads();

    for (int t = 0; t < NT; t++) {
        if (t + 1 < NT) { loadA(t + 1); loadB(t + 1); }
#pragma unroll
        for (int kk = 0; kk < BK; kk++) {
            float a[4], bq[4];
            *(float4*)a  = *(const float4*)&As[kk][rowBase];
            *(float4*)bq = *(const float4*)&Bs[kk][colBase];
#pragma unroll
            for (int i = 0; i < 4; i++)
#pragma unroll
                for (int j = 0; j < 4; j++)
                    acc[i][j] += a[i] * bq[j];
        }
        __syncthreads();
        if (t + 1 < NT) { storeA(); storeB(); __syncthreads(); }
    }

#pragma unroll
    for (int i = 0; i < 4; i++) {
        const int row = m0 + rowBase + i;
#pragma unroll
        for (int j = 0; j < 4; j++) {
            const int col = n0 + colBase + j;
            float v = acc[i][j] + bias[col];
            if (ACT == 0) {
                C[(size_t)row * N + col] = v;
            } else if (ACT == 1) {
                C[(size_t)row * N + col] = sigm(v);
            } else {
                float c = sigm(v);
                C[(size_t)row * N + col] = c;
                S[(size_t)row * N + col] = c * (1.0f - c);
            }
        }
    }
}

// ============================================================================
extern "C" void kernel_launch(void* const* d_in, const int* in_sizes, int n_in,
                              void* d_out, int out_size) {
    const float* x   = (const float*)d_in[0];
    const float* W1  = (const float*)d_in[1];
    const float* b1  = (const float*)d_in[2];
    const float* W2  = (const float*)d_in[3];
    const float* b2  = (const float*)d_in[4];
    const float* b3  = (const float*)d_in[5];
    const float* b_r = (const float*)d_in[6];

    float* out     = (float*)d_out;
    float* recover = out;                              // [B, D]
    float* c2      = out + (size_t)B_ * D_;            // [B, H2]
    float* jac     = c2 + (size_t)B_ * H2_;            // [B, H2, D]

    float *c1, *s1p, *s2p, *c3;
    __half *w1t_hi, *w1t_lo, *a_hi;
    cudaGetSymbolAddress((void**)&c1,  g_c1);
    cudaGetSymbolAddress((void**)&s1p, g_s1p);
    cudaGetSymbolAddress((void**)&s2p, g_s2p);
    cudaGetSymbolAddress((void**)&c3,  g_c3);
    cudaGetSymbolAddress((void**)&w1t_hi, g_w1t_hi);
    cudaGetSymbolAddress((void**)&w1t_lo, g_w1t_lo);
    cudaGetSymbolAddress((void**)&a_hi, g_a_hi);

    cudaFuncSetAttribute(jac_mma_kernel,
                         cudaFuncAttributeMaxDynamicSharedMemorySize, JAC_SMEM);

    dim3 blk(256);

    // W1 -> W1T hi/lo fp16 split (independent of activations)
    w1_split_kernel<<<dim3(H1_ / 32, D_ / 32), dim3(32, 8)>>>(W1, w1t_hi, w1t_lo);

    // c1 = sigmoid(x @ W1^T + b1); s1p = c1*(1-c1)     [512x512, K=1024]
    sgemm64<2, true><<<dim3(H1_ / 64, B_ / 64), blk>>>(x, W1, b1, c1, s1p,
                                                       B_, H1_, D_);
    // c2 = sigmoid(c1 @ W2^T + b2); s2p = c2*(1-c2)    [512x128, K=512]
    sgemm64<2, true><<<dim3(H2_ / 64, B_ / 64), blk>>>(c1, W2, b2, c2, s2p,
                                                       B_, H2_, H1_);
    // A[b] = fp16(W2 . s1p[b])
    a_split_kernel<<<(int)(((size_t)B_ * H2_ * H1_) / 8 / 256), blk>>>(W2, s1p,
                                                                       a_hi);
    // Jac via mma.sync fp16 2-pass                     [512 x (128x1024), K=512]
    jac_mma_kernel<<<dim3(D_ / 256, B_), blk, JAC_SMEM>>>(a_hi, w1t_hi, w1t_lo,
                                                          s2p, jac);
    // c3 = sigmoid(c2 @ W2 + b3)                        [512x512, K=128]
    sgemm64<1, false><<<dim3(H1_ / 64, B_ / 64), blk>>>(c2, W2, b3, c3, nullptr,
                                                        B_, H1_, H2_);
    // recover = c3 @ W1 + b_r                           [512x1024, K=512]
    sgemm64<0, false><<<dim3(D_ / 64, B_ / 64), blk>>>(c3, W1, b_r, recover,
                                                       nullptr, B_, D_, H1_);
}

// round 7
// speedup vs baseline: 3.6798x; 1.3764x over previous
#include <cuda_runtime.h>
#include <cuda_fp16.h>
#include <cstdint>

#define B_  512
#define D_  1024
#define H1_ 512
#define H2_ 128

// ---- scratch (device globals: allocation-free rule) ----
__device__ float g_c1 [B_ * H1_];
__device__ float g_s1p[B_ * H1_];
__device__ float g_s2p[B_ * H2_];
__device__ float g_c3 [B_ * H1_];
__device__ __half g_w1t[D_ * H1_];                     // fp16(W1^T), [D][H1]
__device__ __half g_a_hi[(size_t)B_ * H2_ * H1_];      // fp16(W2 . s1p[b])

__device__ __forceinline__ float sigm(float v) { return 1.0f / (1.0f + expf(-v)); }

__device__ __forceinline__ uint32_t smem_u32(const void* p) {
    uint32_t a;
    asm("{ .reg .u64 t; cvta.to.shared.u64 t, %1; cvt.u32.u64 %0, t; }" : "=r"(a) : "l"(p));
    return a;
}
__device__ __forceinline__ uint32_t packh2(float a, float b) {
    __half2 t = __floats2half2_rn(a, b);
    return *reinterpret_cast<uint32_t*>(&t);
}
__device__ __forceinline__ void cp16(uint32_t dst, const void* src) {
    asm volatile("cp.async.cg.shared.global [%0], [%1], 16;" :: "r"(dst), "l"(src));
}
__device__ __forceinline__ void ldm_x4(uint32_t* r, uint32_t addr) {
    asm volatile("ldmatrix.sync.aligned.m8n8.x4.shared.b16 {%0,%1,%2,%3}, [%4];"
                 : "=r"(r[0]), "=r"(r[1]), "=r"(r[2]), "=r"(r[3]) : "r"(addr));
}
__device__ __forceinline__ void mma_f16(float* c, const uint32_t* a,
                                        uint32_t b0, uint32_t b1) {
    asm volatile("mma.sync.aligned.m16n8k16.row.col.f32.f16.f16.f32 "
                 "{%0,%1,%2,%3}, {%4,%5,%6,%7}, {%8,%9}, {%0,%1,%2,%3};"
                 : "+f"(c[0]), "+f"(c[1]), "+f"(c[2]), "+f"(c[3])
                 : "r"(a[0]), "r"(a[1]), "r"(a[2]), "r"(a[3]), "r"(b0), "r"(b1));
}

// ============================================================================
// W1 convert+transpose: W1 [H1, D] f32 -> fp16 W1T [D][H1]
// ============================================================================
__global__ __launch_bounds__(256)
void w1_split_kernel(const float* __restrict__ W1, __half* __restrict__ hi) {
    __shared__ float t[32][33];
    const int tx = threadIdx.x, ty = threadIdx.y;
    const int k0 = blockIdx.x * 32, d0 = blockIdx.y * 32;
#pragma unroll
    for (int j = 0; j < 4; j++)
        t[ty + 8 * j][tx] = W1[(size_t)(k0 + ty + 8 * j) * D_ + d0 + tx];
    __syncthreads();
#pragma unroll
    for (int j = 0; j < 4; j++) {
        const int dr = ty + 8 * j;
        hi[(size_t)(d0 + dr) * H1_ + k0 + tx] = __float2half_rn(t[tx][dr]);
    }
}

// ============================================================================
// A: A[b,h,k] = fp16(W2[h,k] * s1p[b,k])
// ============================================================================
__global__ __launch_bounds__(256)
void a_split_kernel(const float* __restrict__ W2, const float* __restrict__ s1p,
                    __half* __restrict__ hi) {
    const size_t idx = ((size_t)blockIdx.x * 256 + threadIdx.x) * 8;
    const int k = (int)(idx & (H1_ - 1));
    const int h = (int)((idx >> 9) & (H2_ - 1));
    const int b = (int)(idx >> 16);
    const float* wr = W2 + (size_t)h * H1_ + k;
    const float* sr = s1p + (size_t)b * H1_ + k;
    float4 w0 = *(const float4*)wr;
    float4 w1 = *(const float4*)(wr + 4);
    float4 q0 = *(const float4*)sr;
    float4 q1 = *(const float4*)(sr + 4);
    uint32_t hp[4];
    hp[0] = packh2(w0.x * q0.x, w0.y * q0.y);
    hp[1] = packh2(w0.z * q0.z, w0.w * q0.w);
    hp[2] = packh2(w1.x * q1.x, w1.y * q1.y);
    hp[3] = packh2(w1.z * q1.z, w1.w * q1.w);
    *(uint4*)(hi + idx) = make_uint4(hp[0], hp[1], hp[2], hp[3]);
}

// ============================================================================
// Jac GEMM via mma.sync fp16, single pass: D = Ah*Bh (errs ~3e-4 norm-rel).
// CTA = (batch b, 256-wide n tile): C[128,256] = A'[128,512] @ W1T^T[512,256].
// BK=32, 4-stage cp.async pipeline, ONE __syncthreads per k-iter.
// 8 warps, warp tile 64x64.
// Stage: Ah[128][40] | Bh[256][40]   (fp16, 80B padded rows)
// ============================================================================
static constexpr int A_TILE  = 10240;          // 128*40*2
static constexpr int BT_TILE = 20480;          // 256*40*2
static constexpr int STAGE_B = A_TILE + BT_TILE;           // 30720
static constexpr int JAC_SMEM = 4 * STAGE_B;               // 122880

__global__ __launch_bounds__(256, 1)
void jac_mma_kernel(const __half* __restrict__ a_hi,
                    const __half* __restrict__ w1t,
                    const float* __restrict__ s2p,
                    float* __restrict__ jac) {
    extern __shared__ char smem[];
    const uint32_t sb = smem_u32(smem);
    const int tid = threadIdx.x;
    const int wid = tid >> 5;
    const int lane = tid & 31;
    const int wm = wid >> 2;           // 0..1  (64 rows each)
    const int wn = wid & 3;            // 0..3  (64 cols each)
    const int b  = blockIdx.y;
    const int n0 = blockIdx.x * 256;

    const __half* Ah = a_hi + (size_t)b * (H2_ * H1_);
    const __half* Bh = w1t + (size_t)n0 * H1_;

    float acc[4][8][4] = {};

    // ---- async stage loader: 1536 16B chunks, 6 per thread ----
    // map: [0,512) Ah | [512,1536) Bh
    auto load_stage = [&](int it, int slot) {
        const int k0 = it * 32;
        const uint32_t base = sb + slot * STAGE_B;
#pragma unroll
        for (int q = 0; q < 6; q++) {
            const int c = tid + q * 256;
            const __half* src;
            uint32_t dst;
            if (c < 512) {                        // Ah: 128 rows x 4 segs
                const int row = c >> 2, seg = c & 3;
                src = Ah + (size_t)row * H1_ + k0 + seg * 8;
                dst = base + row * 80 + seg * 16;
            } else {                              // Bh: 256 rows x 4 segs
                const int ci = c - 512;
                const int row = ci >> 2, seg = ci & 3;
                src = Bh + (size_t)row * H1_ + k0 + seg * 8;
                dst = base + A_TILE + row * 80 + seg * 16;
            }
            cp16(dst, src);
        }
        asm volatile("cp.async.commit_group;" ::: "memory");
    };

    // ldmatrix lane addressing
    const int mi = lane >> 3;
    const int a_r  = (lane & 7) + 8 * (mi & 1);
    const int a_cb = (mi >> 1) * 16;
    const int b_r  = (mi >> 1) * 8 + (lane & 7);
    const int b_cb = (mi & 1) * 16;

    load_stage(0, 0);
    load_stage(1, 1);
    load_stage(2, 2);

    for (int it = 0; it < 16; it++) {
        if (it < 14)       asm volatile("cp.async.wait_group 2;" ::: "memory");
        else if (it == 14) asm volatile("cp.async.wait_group 1;" ::: "memory");
        else               asm volatile("cp.async.wait_group 0;" ::: "memory");
        __syncthreads();

        if (it + 3 < 16) load_stage(it + 3, (it + 3) & 3);

        const uint32_t stage = sb + (it & 3) * STAGE_B;
#pragma unroll
        for (int ks = 0; ks < 2; ks++) {
            const int kb2 = ks * 32;               // byte offset of k-step
            uint32_t ah[4][4], bh[4][4];
#pragma unroll
            for (int mt = 0; mt < 4; mt++) {
                const uint32_t ao = (uint32_t)((wm * 64 + mt * 16 + a_r) * 80 + kb2 + a_cb);
                ldm_x4(ah[mt], stage + ao);
            }
#pragma unroll
            for (int np = 0; np < 4; np++) {
                const uint32_t bo = (uint32_t)((wn * 64 + np * 16 + b_r) * 80 + kb2 + b_cb);
                ldm_x4(bh[np], stage + A_TILE + bo);
            }
#pragma unroll
            for (int mt = 0; mt < 4; mt++)
#pragma unroll
                for (int nt = 0; nt < 8; nt++) {
                    const int np = nt >> 1, hq = (nt & 1) * 2;
                    mma_f16(acc[mt][nt], ah[mt], bh[np][hq], bh[np][hq + 1]);
                }
        }
    }

    // ---- epilogue: scale rows by s2p[b,row], store float2 ----
    const int g = lane >> 2;
    const int cq = 2 * (lane & 3);
#pragma unroll
    for (int mt = 0; mt < 4; mt++) {
        const int r0 = wm * 64 + mt * 16 + g;
        const float s0 = s2p[(size_t)b * H2_ + r0];
        const float s1 = s2p[(size_t)b * H2_ + r0 + 8];
        float* row0 = jac + ((size_t)b * H2_ + r0) * D_ + n0;
        float* row1 = row0 + 8 * D_;
#pragma unroll
        for (int nt = 0; nt < 8; nt++) {
            const int col = wn * 64 + nt * 8 + cq;
            float2 v0 = make_float2(acc[mt][nt][0] * s0, acc[mt][nt][1] * s0);
            float2 v1 = make_float2(acc[mt][nt][2] * s1, acc[mt][nt][3] * s1);
            *(float2*)(row0 + col) = v0;
            *(float2*)(row1 + col) = v1;
        }
    }
}

// ============================================================================
// Small generic SGEMM, 64x64x16 tiles, 256 threads, 4x4 microtile (unchanged).
// ============================================================================
template <int ACT, bool TB>
__global__ __launch_bounds__(256)
void sgemm64(const float* __restrict__ A, const float* __restrict__ Bm,
             const float* __restrict__ bias, float* __restrict__ C,
             float* __restrict__ S, int M, int N, int K) {
    constexpr int BM = 64, BN = 64, BK = 16;
    __shared__ __align__(16) float As[BK][BM + 4];
    __shared__ __align__(16) float Bs[BK][BN + 4];

    const int tid = threadIdx.x;
    const int m0 = blockIdx.y * BM;
    const int n0 = blockIdx.x * BN;

    const int ak = tid & 15;
    const int am = tid >> 4;
    const int rowBase = (tid >> 4) * 4;
    const int colBase = (tid & 15) * 4;

    float acc[4][4] = {};
    float ra[4], rb[4];
    const int NT = K / BK;

    auto loadA = [&](int t) {
        const int kt = t * BK;
#pragma unroll
        for (int j = 0; j < 4; j++)
            ra[j] = A[(size_t)(m0 + am + 16 * j) * K + kt + ak];
    };
    auto loadB = [&](int t) {
        const int kt = t * BK;
        if (TB) {
#pragma unroll
            for (int j = 0; j < 4; j++)
                rb[j] = Bm[(size_t)(n0 + am + 16 * j) * K + kt + ak];
        } else {
#pragma unroll
            for (int j = 0; j < 4; j++)
                rb[j] = Bm[(size_t)(kt + (tid >> 6) + 4 * j) * N + n0 + (tid & 63)];
        }
    };
    auto storeA = [&]() {
#pragma unroll
        for (int j = 0; j < 4; j++) As[ak][am + 16 * j] = ra[j];
    };
    auto storeB = [&]() {
        if (TB) {
#pragma unroll
            for (int j = 0; j < 4; j++) Bs[ak][am + 16 * j] = rb[j];
        } else {
#pragma unroll
            for (int j = 0; j < 4; j++) Bs[(tid >> 6) + 4 * j][tid & 63] = rb[j];
        }
    };

    loadA(0); loadB(0);
    storeA(); storeB();
    __syncthreads();

    for (int t = 0; t < NT; t++) {
        if (t + 1 < NT) { loadA(t + 1); loadB(t + 1); }
#pragma unroll
        for (int kk = 0; kk < BK; kk++) {
            float a[4], bq[4];
            *(float4*)a  = *(const float4*)&As[kk][rowBase];
            *(float4*)bq = *(const float4*)&Bs[kk][colBase];
#pragma unroll
            for (int i = 0; i < 4; i++)
#pragma unroll
                for (int j = 0; j < 4; j++)
                    acc[i][j] += a[i] * bq[j];
        }
        __syncthreads();
        if (t + 1 < NT) { storeA(); storeB(); __syncthreads(); }
    }

#pragma unroll
    for (int i = 0; i < 4; i++) {
        const int row = m0 + rowBase + i;
#pragma unroll
        for (int j = 0; j < 4; j++) {
            const int col = n0 + colBase + j;
            float v = acc[i][j] + bias[col];
            if (ACT == 0) {
                C[(size_t)row * N + col] = v;
            } else if (ACT == 1) {
                C[(size_t)row * N + col] = sigm(v);
            } else {
                float c = sigm(v);
                C[(size_t)row * N + col] = c;
                S[(size_t)row * N + col] = c * (1.0f - c);
            }
        }
    }
}

// ============================================================================
extern "C" void kernel_launch(void* const* d_in, const int* in_sizes, int n_in,
                              void* d_out, int out_size) {
    const float* x   = (const float*)d_in[0];
    const float* W1  = (const float*)d_in[1];
    const float* b1  = (const float*)d_in[2];
    const float* W2  = (const float*)d_in[3];
    const float* b2  = (const float*)d_in[4];
    const float* b3  = (const float*)d_in[5];
    const float* b_r = (const float*)d_in[6];

    float* out     = (float*)d_out;
    float* recover = out;                              // [B, D]
    float* c2      = out + (size_t)B_ * D_;            // [B, H2]
    float* jac     = c2 + (size_t)B_ * H2_;            // [B, H2, D]

    float *c1, *s1p, *s2p, *c3;
    __half *w1t, *a_hi;
    cudaGetSymbolAddress((void**)&c1,  g_c1);
    cudaGetSymbolAddress((void**)&s1p, g_s1p);
    cudaGetSymbolAddress((void**)&s2p, g_s2p);
    cudaGetSymbolAddress((void**)&c3,  g_c3);
    cudaGetSymbolAddress((void**)&w1t, g_w1t);
    cudaGetSymbolAddress((void**)&a_hi, g_a_hi);

    cudaFuncSetAttribute(jac_mma_kernel,
                         cudaFuncAttributeMaxDynamicSharedMemorySize, JAC_SMEM);

    dim3 blk(256);

    // W1 -> fp16 W1T (independent of activations)
    w1_split_kernel<<<dim3(H1_ / 32, D_ / 32), dim3(32, 8)>>>(W1, w1t);

    // c1 = sigmoid(x @ W1^T + b1); s1p = c1*(1-c1)     [512x512, K=1024]
    sgemm64<2, true><<<dim3(H1_ / 64, B_ / 64), blk>>>(x, W1, b1, c1, s1p,
                                                       B_, H1_, D_);
    // c2 = sigmoid(c1 @ W2^T + b2); s2p = c2*(1-c2)    [512x128, K=512]
    sgemm64<2, true><<<dim3(H2_ / 64, B_ / 64), blk>>>(c1, W2, b2, c2, s2p,
                                                       B_, H2_, H1_);
    // A[b] = fp16(W2 . s1p[b])
    a_split_kernel<<<(int)(((size_t)B_ * H2_ * H1_) / 8 / 256), blk>>>(W2, s1p,
                                                                       a_hi);
    // Jac via mma.sync fp16 single pass                [512 x (128x1024), K=512]
    jac_mma_kernel<<<dim3(D_ / 256, B_), blk, JAC_SMEM>>>(a_hi, w1t, s2p, jac);
    // c3 = sigmoid(c2 @ W2 + b3)                        [512x512, K=128]
    sgemm64<1, false><<<dim3(H1_ / 64, B_ / 64), blk>>>(c2, W2, b3, c3, nullptr,
                                                        B_, H1_, H2_);
    // recover = c3 @ W1 + b_r                           [512x1024, K=512]
    sgemm64<0, false><<<dim3(D_ / 64, B_ / 64), blk>>>(c3, W1, b_r, recover,
                                                       nullptr, B_, D_, H1_);
}

// round 8
// speedup vs baseline: 3.8073x; 1.0346x over previous
#include <cuda_runtime.h>
#include <cuda_fp16.h>
#include <cstdint>

#define B_  512
#define D_  1024
#define H1_ 512
#define H2_ 128

// ---- scratch (device globals: allocation-free rule) ----
__device__ float g_c1 [B_ * H1_];
__device__ float g_s1p[B_ * H1_];
__device__ float g_s2p[B_ * H2_];
__device__ float g_c3 [B_ * H1_];
// Fragment-packed operands for jac mma (exact m16n8k16 register layout):
// gA: [b][kt=32][mt=8] tiles, tile = 512B: lane*16B = {a0,a1,a2,a3} (2 fp16 each)
// gB: [n16=64][kt=32] tile-pairs, 512B: lane*16B = {b0s0,b1s0,b0s1,b1s1}
__device__ __half g_a_frag[(size_t)B_ * H2_ * H1_];
__device__ __half g_b_frag[(size_t)D_ * H1_];

__device__ __forceinline__ float sigm(float v) { return 1.0f / (1.0f + expf(-v)); }

__device__ __forceinline__ uint32_t packh2(float a, float b) {
    __half2 t = __floats2half2_rn(a, b);
    return *reinterpret_cast<uint32_t*>(&t);
}
__device__ __forceinline__ void mma_f16(float* c, const uint32_t* a,
                                        uint32_t b0, uint32_t b1) {
    asm volatile("mma.sync.aligned.m16n8k16.row.col.f32.f16.f16.f32 "
                 "{%0,%1,%2,%3}, {%4,%5,%6,%7}, {%8,%9}, {%0,%1,%2,%3};"
                 : "+f"(c[0]), "+f"(c[1]), "+f"(c[2]), "+f"(c[3])
                 : "r"(a[0]), "r"(a[1]), "r"(a[2]), "r"(a[3]), "r"(b0), "r"(b1));
}

// ============================================================================
// B fragment pack: W1 [H1=512 (k), D=1024 (n)] f32 -> g_b_frag.
// Tile (n16, kt): element (k_t, n_t):
//   lane = (n_t%8)*4 + ((k_t%8)>>1), reg j = (k_t>>3) + 2*(n_t>>3), half = k_t&1
// One thread writes one lane's 16B.  tiles = 64*32 = 2048, 8 tiles/block.
// ============================================================================
__global__ __launch_bounds__(256)
void w1_frag_kernel(const float* __restrict__ W1, __half* __restrict__ gB) {
    const int t = blockIdx.x * 8 + (threadIdx.x >> 5);
    const int n16 = t >> 5, kt = t & 31;
    const int lane = threadIdx.x & 31;
    const int n0 = n16 * 16 + (lane >> 2);
    const int kb = kt * 16 + 2 * (lane & 3);

    const float* Wk0 = W1 + (size_t)kb * D_;
    uint32_t p0 = packh2(Wk0[n0],              Wk0[D_ + n0]);
    uint32_t p1 = packh2(Wk0[8 * D_ + n0],     Wk0[9 * D_ + n0]);
    uint32_t p2 = packh2(Wk0[n0 + 8],          Wk0[D_ + n0 + 8]);
    uint32_t p3 = packh2(Wk0[8 * D_ + n0 + 8], Wk0[9 * D_ + n0 + 8]);

    *(uint4*)(gB + (size_t)t * 256 + lane * 8) = make_uint4(p0, p1, p2, p3);
}

// ============================================================================
// A fragment pack: A[b,r,k] = fp16(W2[r,k] * s1p[b,k]) -> g_a_frag.
// Tile (b, kt, mt): element (r_t, k_t):
//   lane = (r_t%8)*4 + ((k_t%8)>>1), reg j = (r_t>>3) + 2*(k_t>>3), half = k_t&1
// Block = (b, kt); warp w handles mt = w. Stores perfectly coalesced.
// ============================================================================
__global__ __launch_bounds__(256)
void a_frag_kernel(const float* __restrict__ W2, const float* __restrict__ s1p,
                   __half* __restrict__ gA) {
    const int b  = blockIdx.x >> 5;
    const int kt = blockIdx.x & 31;
    const int w  = threadIdx.x >> 5;       // mt
    const int lane = threadIdx.x & 31;
    const int r0 = w * 16 + (lane >> 2);
    const int kb = kt * 16 + 2 * (lane & 3);

    const float* s = s1p + (size_t)b * H1_;
    const float s0 = s[kb], s1v = s[kb + 1], s8 = s[kb + 8], s9 = s[kb + 9];
    const float* w2a = W2 + (size_t)r0 * H1_;
    const float* w2b = w2a + 8 * H1_;

    uint32_t p0 = packh2(w2a[kb] * s0,     w2a[kb + 1] * s1v);
    uint32_t p1 = packh2(w2b[kb] * s0,     w2b[kb + 1] * s1v);
    uint32_t p2 = packh2(w2a[kb + 8] * s8, w2a[kb + 9] * s9);
    uint32_t p3 = packh2(w2b[kb + 8] * s8, w2b[kb + 9] * s9);

    const size_t tile = ((size_t)blockIdx.x * 8 + w);
    *(uint4*)(gA + tile * 256 + lane * 8) = make_uint4(p0, p1, p2, p3);
}

// ============================================================================
// Jac GEMM, fragment-direct: no smem, no ldmatrix, no syncs.
// CTA = (batch b, 256-wide n tile); 8 warps, warp tile 64x64.
// Per warp k16-iter: 8x LDG.128 (4 A tiles + 4 B tile-pairs) -> 32x HMMA.
// ============================================================================
__global__ __launch_bounds__(256, 1)
void jac_mma_kernel(const __half* __restrict__ gA,
                    const __half* __restrict__ gB,
                    const float* __restrict__ s2p,
                    float* __restrict__ jac) {
    const int tid = threadIdx.x;
    const int wid = tid >> 5;
    const int lane = tid & 31;
    const int wm = wid >> 2;           // 0..1  (64 rows)
    const int wn = wid & 3;            // 0..3  (64 cols)
    const int b  = blockIdx.y;
    const int n0 = blockIdx.x * 256;

    const __half* Ab = gA + (size_t)b * (32 * 8 * 256);
    const int n16base = (n0 >> 4) + wn * 4;

    float acc[4][8][4] = {};

    #pragma unroll 2
    for (int kt = 0; kt < 32; kt++) {
        uint4 av[4], bv[4];
#pragma unroll
        for (int mt = 0; mt < 4; mt++)
            av[mt] = *(const uint4*)(Ab + ((size_t)kt * 8 + wm * 4 + mt) * 256
                                     + lane * 8);
#pragma unroll
        for (int np = 0; np < 4; np++)
            bv[np] = *(const uint4*)(gB + ((size_t)(n16base + np) * 32 + kt) * 256
                                     + lane * 8);
#pragma unroll
        for (int mt = 0; mt < 4; mt++) {
            const uint32_t* ap = reinterpret_cast<const uint32_t*>(&av[mt]);
#pragma unroll
            for (int np = 0; np < 4; np++) {
                mma_f16(acc[mt][np * 2 + 0], ap, bv[np].x, bv[np].y);
                mma_f16(acc[mt][np * 2 + 1], ap, bv[np].z, bv[np].w);
            }
        }
    }

    // ---- epilogue: scale rows by s2p[b,row], store float2 ----
    const int g = lane >> 2;
    const int cq = 2 * (lane & 3);
#pragma unroll
    for (int mt = 0; mt < 4; mt++) {
        const int r0 = wm * 64 + mt * 16 + g;
        const float s0 = s2p[(size_t)b * H2_ + r0];
        const float s1 = s2p[(size_t)b * H2_ + r0 + 8];
        float* row0 = jac + ((size_t)b * H2_ + r0) * D_ + n0;
        float* row1 = row0 + 8 * D_;
#pragma unroll
        for (int nt = 0; nt < 8; nt++) {
            const int col = wn * 64 + nt * 8 + cq;
            float2 v0 = make_float2(acc[mt][nt][0] * s0, acc[mt][nt][1] * s0);
            float2 v1 = make_float2(acc[mt][nt][2] * s1, acc[mt][nt][3] * s1);
            *(float2*)(row0 + col) = v0;
            *(float2*)(row1 + col) = v1;
        }
    }
}

// ============================================================================
// Small generic SGEMM, 64x64x16 tiles, 256 threads, 4x4 microtile (unchanged).
// ============================================================================
template <int ACT, bool TB>
__global__ __launch_bounds__(256)
void sgemm64(const float* __restrict__ A, const float* __restrict__ Bm,
             const float* __restrict__ bias, float* __restrict__ C,
             float* __restrict__ S, int M, int N, int K) {
    constexpr int BM = 64, BN = 64, BK = 16;
    __shared__ __align__(16) float As[BK][BM + 4];
    __shared__ __align__(16) float Bs[BK][BN + 4];

    const int tid = threadIdx.x;
    const int m0 = blockIdx.y * BM;
    const int n0 = blockIdx.x * BN;

    const int ak = tid & 15;
    const int am = tid >> 4;
    const int rowBase = (tid >> 4) * 4;
    const int colBase = (tid & 15) * 4;

    float acc[4][4] = {};
    float ra[4], rb[4];
    const int NT = K / BK;

    auto loadA = [&](int t) {
        const int kt = t * BK;
#pragma unroll
        for (int j = 0; j < 4; j++)
            ra[j] = A[(size_t)(m0 + am + 16 * j) * K + kt + ak];
    };
    auto loadB = [&](int t) {
        const int kt = t * BK;
        if (TB) {
#pragma unroll
            for (int j = 0; j < 4; j++)
                rb[j] = Bm[(size_t)(n0 + am + 16 * j) * K + kt + ak];
        } else {
#pragma unroll
            for (int j = 0; j < 4; j++)
                rb[j] = Bm[(size_t)(kt + (tid >> 6) + 4 * j) * N + n0 + (tid & 63)];
        }
    };
    auto storeA = [&]() {
#pragma unroll
        for (int j = 0; j < 4; j++) As[ak][am + 16 * j] = ra[j];
    };
    auto storeB = [&]() {
        if (TB) {
#pragma unroll
            for (int j = 0; j < 4; j++) Bs[ak][am + 16 * j] = rb[j];
        } else {
#pragma unroll
            for (int j = 0; j < 4; j++) Bs[(tid >> 6) + 4 * j][tid & 63] = rb[j];
        }
    };

    loadA(0); loadB(0);
    storeA(); storeB();
    __syncthreads();

    for (int t = 0; t < NT; t++) {
        if (t + 1 < NT) { loadA(t + 1); loadB(t + 1); }
#pragma unroll
        for (int kk = 0; kk < BK; kk++) {
            float a[4], bq[4];
            *(float4*)a  = *(const float4*)&As[kk][rowBase];
            *(float4*)bq = *(const float4*)&Bs[kk][colBase];
#pragma unroll
            for (int i = 0; i < 4; i++)
#pragma unroll
                for (int j = 0; j < 4; j++)
                    acc[i][j] += a[i] * bq[j];
        }
        __syncthreads();
        if (t + 1 < NT) { storeA(); storeB(); __syncthreads(); }
    }

#pragma unroll
    for (int i = 0; i < 4; i++) {
        const int row = m0 + rowBase + i;
#pragma unroll
        for (int j = 0; j < 4; j++) {
            const int col = n0 + colBase + j;
            float v = acc[i][j] + bias[col];
            if (ACT == 0) {
                C[(size_t)row * N + col] = v;
            } else if (ACT == 1) {
                C[(size_t)row * N + col] = sigm(v);
            } else {
                float c = sigm(v);
                C[(size_t)row * N + col] = c;
                S[(size_t)row * N + col] = c * (1.0f - c);
            }
        }
    }
}

// ============================================================================
extern "C" void kernel_launch(void* const* d_in, const int* in_sizes, int n_in,
                              void* d_out, int out_size) {
    const float* x   = (const float*)d_in[0];
    const float* W1  = (const float*)d_in[1];
    const float* b1  = (const float*)d_in[2];
    const float* W2  = (const float*)d_in[3];
    const float* b2  = (const float*)d_in[4];
    const float* b3  = (const float*)d_in[5];
    const float* b_r = (const float*)d_in[6];

    float* out     = (float*)d_out;
    float* recover = out;                              // [B, D]
    float* c2      = out + (size_t)B_ * D_;            // [B, H2]
    float* jac     = c2 + (size_t)B_ * H2_;            // [B, H2, D]

    float *c1, *s1p, *s2p, *c3;
    __half *a_frag, *b_frag;
    cudaGetSymbolAddress((void**)&c1,  g_c1);
    cudaGetSymbolAddress((void**)&s1p, g_s1p);
    cudaGetSymbolAddress((void**)&s2p, g_s2p);
    cudaGetSymbolAddress((void**)&c3,  g_c3);
    cudaGetSymbolAddress((void**)&a_frag, g_a_frag);
    cudaGetSymbolAddress((void**)&b_frag, g_b_frag);

    dim3 blk(256);

    // W1 -> fragment-packed fp16 B operand (independent of activations)
    w1_frag_kernel<<<(64 * 32) / 8, blk>>>(W1, b_frag);

    // c1 = sigmoid(x @ W1^T + b1); s1p = c1*(1-c1)     [512x512, K=1024]
    sgemm64<2, true><<<dim3(H1_ / 64, B_ / 64), blk>>>(x, W1, b1, c1, s1p,
                                                       B_, H1_, D_);
    // c2 = sigmoid(c1 @ W2^T + b2); s2p = c2*(1-c2)    [512x128, K=512]
    sgemm64<2, true><<<dim3(H2_ / 64, B_ / 64), blk>>>(c1, W2, b2, c2, s2p,
                                                       B_, H2_, H1_);
    // A[b] = fp16(W2 . s1p[b]) fragment-packed
    a_frag_kernel<<<B_ * 32, blk>>>(W2, s1p, a_frag);
    // Jac via fragment-direct mma.sync                 [512 x (128x1024), K=512]
    jac_mma_kernel<<<dim3(D_ / 256, B_), blk>>>(a_frag, b_frag, s2p, jac);
    // c3 = sigmoid(c2 @ W2 + b3)                        [512x512, K=128]
    sgemm64<1, false><<<dim3(H1_ / 64, B_ / 64), blk>>>(c2, W2, b3, c3, nullptr,
                                                        B_, H1_, H2_);
    // recover = c3 @ W1 + b_r                           [512x1024, K=512]
    sgemm64<0, false><<<dim3(D_ / 64, B_ / 64), blk>>>(c3, W1, b_r, recover,
                                                       nullptr, B_, D_, H1_);
}

// round 9
// speedup vs baseline: 4.3397x; 1.1399x over previous
#include <cuda_runtime.h>
#include <cuda_fp16.h>
#include <cstdint>

#define B_  512
#define D_  1024
#define H1_ 512
#define H2_ 128

// ---- scratch (device globals: allocation-free rule) ----
__device__ float g_c1 [B_ * H1_];
__device__ float g_s1p[B_ * H1_];
__device__ float g_s2p[B_ * H2_];
__device__ float g_c3 [B_ * H1_];
// Fragment-packed operands (exact m16n8k16 register layout):
__device__ __half g_a_frag[(size_t)B_ * H2_ * H1_];
__device__ __half g_b_frag[(size_t)D_ * H1_];
__device__ float  g_w2_frag[H2_ * H1_];                // W2 in fragment order, f32
__device__ __half g_c3_frag[B_ * H1_];                 // c3 fragment-packed

__device__ __forceinline__ float sigm(float v) { return 1.0f / (1.0f + expf(-v)); }

__device__ __forceinline__ uint32_t packh2(float a, float b) {
    __half2 t = __floats2half2_rn(a, b);
    return *reinterpret_cast<uint32_t*>(&t);
}
__device__ __forceinline__ void mma_f16(float* c, const uint32_t* a,
                                        uint32_t b0, uint32_t b1) {
    asm volatile("mma.sync.aligned.m16n8k16.row.col.f32.f16.f16.f32 "
                 "{%0,%1,%2,%3}, {%4,%5,%6,%7}, {%8,%9}, {%0,%1,%2,%3};"
                 : "+f"(c[0]), "+f"(c[1]), "+f"(c[2]), "+f"(c[3])
                 : "r"(a[0]), "r"(a[1]), "r"(a[2]), "r"(a[3]), "r"(b0), "r"(b1));
}

// ============================================================================
// B fragment pack: W1 [H1 (k), D (n)] f32 -> g_b_frag (tile = 512B).
// ============================================================================
__global__ __launch_bounds__(256)
void w1_frag_kernel(const float* __restrict__ W1, __half* __restrict__ gB) {
    const int t = blockIdx.x * 8 + (threadIdx.x >> 5);
    const int n16 = t >> 5, kt = t & 31;
    const int lane = threadIdx.x & 31;
    const int n0 = n16 * 16 + (lane >> 2);
    const int kb = kt * 16 + 2 * (lane & 3);

    const float* Wk0 = W1 + (size_t)kb * D_;
    uint32_t p0 = packh2(Wk0[n0],              Wk0[D_ + n0]);
    uint32_t p1 = packh2(Wk0[8 * D_ + n0],     Wk0[9 * D_ + n0]);
    uint32_t p2 = packh2(Wk0[n0 + 8],          Wk0[D_ + n0 + 8]);
    uint32_t p3 = packh2(Wk0[8 * D_ + n0 + 8], Wk0[9 * D_ + n0 + 8]);

    *(uint4*)(gB + (size_t)t * 256 + lane * 8) = make_uint4(p0, p1, p2, p3);
}

// ============================================================================
// W2 fragment pre-permute (once; input-only): scattered reads here so that
// a_frag_kernel becomes fully coalesced.
// Layout: per tile (kt, mt), lane: 8 floats =
//   {w2a[kb],w2a[kb+1],w2b[kb],w2b[kb+1], w2a[kb+8],w2a[kb+9],w2b[kb+8],w2b[kb+9]}
// ============================================================================
__global__ __launch_bounds__(256)
void w2_frag_kernel(const float* __restrict__ W2, float* __restrict__ w2f) {
    const int kt = blockIdx.x;             // 0..31
    const int mt = threadIdx.x >> 5;       // 0..7
    const int lane = threadIdx.x & 31;
    const int r0 = mt * 16 + (lane >> 2);
    const int kb = kt * 16 + 2 * (lane & 3);
    const float* w2a = W2 + (size_t)r0 * H1_;
    const float* w2b = w2a + 8 * H1_;
    float* dst = w2f + ((size_t)kt * 8 + mt) * 256 + lane * 8;
    *(float4*)(dst)     = make_float4(w2a[kb],     w2a[kb + 1], w2b[kb],     w2b[kb + 1]);
    *(float4*)(dst + 4) = make_float4(w2a[kb + 8], w2a[kb + 9], w2b[kb + 8], w2b[kb + 9]);
}

// ============================================================================
// A fragment pack (coalesced): A = fp16(w2f * s1p[b]) in fragment order.
// ============================================================================
__global__ __launch_bounds__(256)
void a_frag_kernel(const float* __restrict__ w2f, const float* __restrict__ s1p,
                   __half* __restrict__ gA) {
    const int b  = blockIdx.x >> 5;
    const int kt = blockIdx.x & 31;
    const int w  = threadIdx.x >> 5;       // mt
    const int lane = threadIdx.x & 31;
    const int kb = kt * 16 + 2 * (lane & 3);

    const float* s = s1p + (size_t)b * H1_;
    const float s0 = s[kb], s1v = s[kb + 1], s8 = s[kb + 8], s9 = s[kb + 9];
    const float* src = w2f + ((size_t)kt * 8 + w) * 256 + lane * 8;
    float4 f0 = *(const float4*)(src);
    float4 f1 = *(const float4*)(src + 4);

    uint32_t p0 = packh2(f0.x * s0, f0.y * s1v);
    uint32_t p1 = packh2(f0.z * s0, f0.w * s1v);
    uint32_t p2 = packh2(f1.x * s8, f1.y * s9);
    uint32_t p3 = packh2(f1.z * s8, f1.w * s9);

    const size_t tile = ((size_t)blockIdx.x * 8 + w);
    *(uint4*)(gA + tile * 256 + lane * 8) = make_uint4(p0, p1, p2, p3);
}

// ============================================================================
// c3 fragment pack: c3 [512,512] f32 -> A-fragments [kt=32][mt=32].
// ============================================================================
__global__ __launch_bounds__(256)
void c3_frag_kernel(const float* __restrict__ c3, __half* __restrict__ gA) {
    const int t = blockIdx.x * 8 + (threadIdx.x >> 5);   // tile id
    const int kt = t >> 5, mt = t & 31;
    const int lane = threadIdx.x & 31;
    const int r0 = mt * 16 + (lane >> 2);
    const int kb = kt * 16 + 2 * (lane & 3);
    const float* ca = c3 + (size_t)r0 * H1_;
    const float* cb = ca + 8 * H1_;
    uint32_t p0 = packh2(ca[kb],     ca[kb + 1]);
    uint32_t p1 = packh2(cb[kb],     cb[kb + 1]);
    uint32_t p2 = packh2(ca[kb + 8], ca[kb + 9]);
    uint32_t p3 = packh2(cb[kb + 8], cb[kb + 9]);
    *(uint4*)(gA + (size_t)t * 256 + lane * 8) = make_uint4(p0, p1, p2, p3);
}

// ============================================================================
// Jac GEMM, fragment-direct (unchanged from R8).
// ============================================================================
__global__ __launch_bounds__(256, 1)
void jac_mma_kernel(const __half* __restrict__ gA,
                    const __half* __restrict__ gB,
                    const float* __restrict__ s2p,
                    float* __restrict__ jac) {
    const int tid = threadIdx.x;
    const int wid = tid >> 5;
    const int lane = tid & 31;
    const int wm = wid >> 2;
    const int wn = wid & 3;
    const int b  = blockIdx.y;
    const int n0 = blockIdx.x * 256;

    const __half* Ab = gA + (size_t)b * (32 * 8 * 256);
    const int n16base = (n0 >> 4) + wn * 4;

    float acc[4][8][4] = {};

    #pragma unroll 2
    for (int kt = 0; kt < 32; kt++) {
        uint4 av[4], bv[4];
#pragma unroll
        for (int mt = 0; mt < 4; mt++)
            av[mt] = *(const uint4*)(Ab + ((size_t)kt * 8 + wm * 4 + mt) * 256
                                     + lane * 8);
#pragma unroll
        for (int np = 0; np < 4; np++)
            bv[np] = *(const uint4*)(gB + ((size_t)(n16base + np) * 32 + kt) * 256
                                     + lane * 8);
#pragma unroll
        for (int mt = 0; mt < 4; mt++) {
            const uint32_t* ap = reinterpret_cast<const uint32_t*>(&av[mt]);
#pragma unroll
            for (int np = 0; np < 4; np++) {
                mma_f16(acc[mt][np * 2 + 0], ap, bv[np].x, bv[np].y);
                mma_f16(acc[mt][np * 2 + 1], ap, bv[np].z, bv[np].w);
            }
        }
    }

    const int g = lane >> 2;
    const int cq = 2 * (lane & 3);
#pragma unroll
    for (int mt = 0; mt < 4; mt++) {
        const int r0 = wm * 64 + mt * 16 + g;
        const float s0 = s2p[(size_t)b * H2_ + r0];
        const float s1 = s2p[(size_t)b * H2_ + r0 + 8];
        float* row0 = jac + ((size_t)b * H2_ + r0) * D_ + n0;
        float* row1 = row0 + 8 * D_;
#pragma unroll
        for (int nt = 0; nt < 8; nt++) {
            const int col = wn * 64 + nt * 8 + cq;
            *(float2*)(row0 + col) = make_float2(acc[mt][nt][0] * s0, acc[mt][nt][1] * s0);
            *(float2*)(row1 + col) = make_float2(acc[mt][nt][2] * s1, acc[mt][nt][3] * s1);
        }
    }
}

// ============================================================================
// recover = c3 @ W1 + b_r via fragment-direct mma; reuses g_b_frag.
// grid (D/256, M/128); A tiles [kt*32 + mtile].
// ============================================================================
__global__ __launch_bounds__(256, 1)
void recover_mma_kernel(const __half* __restrict__ gA,
                        const __half* __restrict__ gB,
                        const float* __restrict__ b_r,
                        float* __restrict__ out) {
    const int tid = threadIdx.x;
    const int wid = tid >> 5;
    const int lane = tid & 31;
    const int wm = wid >> 2;
    const int wn = wid & 3;
    const int m0 = blockIdx.y * 128;
    const int n0 = blockIdx.x * 256;

    const int mtb = (m0 >> 4) + wm * 4;
    const int n16base = (n0 >> 4) + wn * 4;

    float acc[4][8][4] = {};

    #pragma unroll 2
    for (int kt = 0; kt < 32; kt++) {
        uint4 av[4], bv[4];
#pragma unroll
        for (int mt = 0; mt < 4; mt++)
            av[mt] = *(const uint4*)(gA + ((size_t)kt * 32 + mtb + mt) * 256
                                     + lane * 8);
#pragma unroll
        for (int np = 0; np < 4; np++)
            bv[np] = *(const uint4*)(gB + ((size_t)(n16base + np) * 32 + kt) * 256
                                     + lane * 8);
#pragma unroll
        for (int mt = 0; mt < 4; mt++) {
            const uint32_t* ap = reinterpret_cast<const uint32_t*>(&av[mt]);
#pragma unroll
            for (int np = 0; np < 4; np++) {
                mma_f16(acc[mt][np * 2 + 0], ap, bv[np].x, bv[np].y);
                mma_f16(acc[mt][np * 2 + 1], ap, bv[np].z, bv[np].w);
            }
        }
    }

    const int g = lane >> 2;
    const int cq = 2 * (lane & 3);
#pragma unroll
    for (int mt = 0; mt < 4; mt++) {
        const int r0 = m0 + wm * 64 + mt * 16 + g;
        float* row0 = out + (size_t)r0 * D_ + n0;
        float* row1 = row0 + 8 * D_;
#pragma unroll
        for (int nt = 0; nt < 8; nt++) {
            const int col = wn * 64 + nt * 8 + cq;
            const float bc0 = b_r[n0 + col], bc1 = b_r[n0 + col + 1];
            *(float2*)(row0 + col) = make_float2(acc[mt][nt][0] + bc0, acc[mt][nt][1] + bc1);
            *(float2*)(row1 + col) = make_float2(acc[mt][nt][2] + bc0, acc[mt][nt][3] + bc1);
        }
    }
}

// ============================================================================
// Small generic SGEMM (scalar), unchanged.
// ============================================================================
template <int ACT, bool TB>
__global__ __launch_bounds__(256)
void sgemm64(const float* __restrict__ A, const float* __restrict__ Bm,
             const float* __restrict__ bias, float* __restrict__ C,
             float* __restrict__ S, int M, int N, int K) {
    constexpr int BM = 64, BN = 64, BK = 16;
    __shared__ __align__(16) float As[BK][BM + 4];
    __shared__ __align__(16) float Bs[BK][BN + 4];

    const int tid = threadIdx.x;
    const int m0 = blockIdx.y * BM;
    const int n0 = blockIdx.x * BN;

    const int ak = tid & 15;
    const int am = tid >> 4;
    const int rowBase = (tid >> 4) * 4;
    const int colBase = (tid & 15) * 4;

    float acc[4][4] = {};
    float ra[4], rb[4];
    const int NT = K / BK;

    auto loadA = [&](int t) {
        const int kt = t * BK;
#pragma unroll
        for (int j = 0; j < 4; j++)
            ra[j] = A[(size_t)(m0 + am + 16 * j) * K + kt + ak];
    };
    auto loadB = [&](int t) {
        const int kt = t * BK;
        if (TB) {
#pragma unroll
            for (int j = 0; j < 4; j++)
                rb[j] = Bm[(size_t)(n0 + am + 16 * j) * K + kt + ak];
        } else {
#pragma unroll
            for (int j = 0; j < 4; j++)
                rb[j] = Bm[(size_t)(kt + (tid >> 6) + 4 * j) * N + n0 + (tid & 63)];
        }
    };
    auto storeA = [&]() {
#pragma unroll
        for (int j = 0; j < 4; j++) As[ak][am + 16 * j] = ra[j];
    };
    auto storeB = [&]() {
        if (TB) {
#pragma unroll
            for (int j = 0; j < 4; j++) Bs[ak][am + 16 * j] = rb[j];
        } else {
#pragma unroll
            for (int j = 0; j < 4; j++) Bs[(tid >> 6) + 4 * j][tid & 63] = rb[j];
        }
    };

    loadA(0); loadB(0);
    storeA(); storeB();
    __syncthreads();

    for (int t = 0; t < NT; t++) {
        if (t + 1 < NT) { loadA(t + 1); loadB(t + 1); }
#pragma unroll
        for (int kk = 0; kk < BK; kk++) {
            float a[4], bq[4];
            *(float4*)a  = *(const float4*)&As[kk][rowBase];
            *(float4*)bq = *(const float4*)&Bs[kk][colBase];
#pragma unroll
            for (int i = 0; i < 4; i++)
#pragma unroll
                for (int j = 0; j < 4; j++)
                    acc[i][j] += a[i] * bq[j];
        }
        __syncthreads();
        if (t + 1 < NT) { storeA(); storeB(); __syncthreads(); }
    }

#pragma unroll
    for (int i = 0; i < 4; i++) {
        const int row = m0 + rowBase + i;
#pragma unroll
        for (int j = 0; j < 4; j++) {
            const int col = n0 + colBase + j;
            float v = acc[i][j] + bias[col];
            if (ACT == 0) {
                C[(size_t)row * N + col] = v;
            } else if (ACT == 1) {
                C[(size_t)row * N + col] = sigm(v);
            } else {
                float c = sigm(v);
                C[(size_t)row * N + col] = c;
                S[(size_t)row * N + col] = c * (1.0f - c);
            }
        }
    }
}

// ============================================================================
// Stream/event aux (created once, on the first — non-captured — call).
// ============================================================================
struct Aux {
    cudaStream_t s1;
    cudaEvent_t e0, e1, e2, e3, e4;
    Aux() {
        cudaStreamCreateWithFlags(&s1, cudaStreamNonBlocking);
        cudaEventCreateWithFlags(&e0, cudaEventDisableTiming);
        cudaEventCreateWithFlags(&e1, cudaEventDisableTiming);
        cudaEventCreateWithFlags(&e2, cudaEventDisableTiming);
        cudaEventCreateWithFlags(&e3, cudaEventDisableTiming);
        cudaEventCreateWithFlags(&e4, cudaEventDisableTiming);
    }
};

extern "C" void kernel_launch(void* const* d_in, const int* in_sizes, int n_in,
                              void* d_out, int out_size) {
    const float* x   = (const float*)d_in[0];
    const float* W1  = (const float*)d_in[1];
    const float* b1  = (const float*)d_in[2];
    const float* W2  = (const float*)d_in[3];
    const float* b2  = (const float*)d_in[4];
    const float* b3  = (const float*)d_in[5];
    const float* b_r = (const float*)d_in[6];

    float* out     = (float*)d_out;
    float* recover = out;                              // [B, D]
    float* c2      = out + (size_t)B_ * D_;            // [B, H2]
    float* jac     = c2 + (size_t)B_ * H2_;            // [B, H2, D]

    float *c1, *s1p, *s2p, *c3, *w2f;
    __half *a_frag, *b_frag, *c3_frag;
    cudaGetSymbolAddress((void**)&c1,  g_c1);
    cudaGetSymbolAddress((void**)&s1p, g_s1p);
    cudaGetSymbolAddress((void**)&s2p, g_s2p);
    cudaGetSymbolAddress((void**)&c3,  g_c3);
    cudaGetSymbolAddress((void**)&w2f, g_w2_frag);
    cudaGetSymbolAddress((void**)&a_frag, g_a_frag);
    cudaGetSymbolAddress((void**)&b_frag, g_b_frag);
    cudaGetSymbolAddress((void**)&c3_frag, g_c3_frag);

    static Aux aux;                    // first call is outside graph capture
    cudaStream_t s0 = 0, s1 = aux.s1;
    dim3 blk(256);

    // fork side stream
    cudaEventRecord(aux.e0, s0);
    cudaStreamWaitEvent(s1, aux.e0, 0);

    // side: input-only fragment preps (independent of activations)
    w1_frag_kernel<<<(64 * 32) / 8, blk, 0, s1>>>(W1, b_frag);
    w2_frag_kernel<<<32, blk, 0, s1>>>(W2, w2f);

    // main: c1 = sigmoid(x @ W1^T + b1); s1p                [512x512, K=1024]
    sgemm64<2, true><<<dim3(H1_ / 64, B_ / 64), blk, 0, s0>>>(x, W1, b1, c1, s1p,
                                                              B_, H1_, D_);
    cudaEventRecord(aux.e1, s0);

    // side: A fragments (needs s1p + w2f)
    cudaStreamWaitEvent(s1, aux.e1, 0);
    a_frag_kernel<<<B_ * 32, blk, 0, s1>>>(w2f, s1p, a_frag);
    cudaEventRecord(aux.e2, s1);

    // main: c2 = sigmoid(c1 @ W2^T + b2); s2p               [512x128, K=512]
    sgemm64<2, true><<<dim3(H2_ / 64, B_ / 64), blk, 0, s0>>>(c1, W2, b2, c2, s2p,
                                                              B_, H2_, H1_);
    cudaEventRecord(aux.e3, s0);

    // side: c3 = sigmoid(c2 @ W2 + b3); pack; recover       (after c2)
    cudaStreamWaitEvent(s1, aux.e3, 0);
    sgemm64<1, false><<<dim3(H1_ / 64, B_ / 64), blk, 0, s1>>>(c2, W2, b3, c3,
                                                               nullptr, B_, H1_, H2_);
    c3_frag_kernel<<<(32 * 32) / 8, blk, 0, s1>>>(c3, c3_frag);
    recover_mma_kernel<<<dim3(D_ / 256, B_ / 128), blk, 0, s1>>>(c3_frag, b_frag,
                                                                 b_r, recover);
    cudaEventRecord(aux.e4, s1);

    // main: jac (needs a_frag + b_frag [covered by e2] and s2p [in-order])
    cudaStreamWaitEvent(s0, aux.e2, 0);
    jac_mma_kernel<<<dim3(D_ / 256, B_), blk, 0, s0>>>(a_frag, b_frag, s2p, jac);

    // join
    cudaStreamWaitEvent(s0, aux.e4, 0);
}